// round 8
// baseline (speedup 1.0000x reference)
#include <cuda_runtime.h>
#include <cstdint>

#define N_NODES 50000
#define N_EDGES 600000
#define IN_DIM  64
#define HIDDEN  128
#define N_REL   10
#define N_LAYERS 6
#define N_GRAPHS 64
#define LN_EPS  1e-5f

#define KTOT    (HIDDEN + N_REL * HIDDEN)   // 1408
#define NRN     (N_REL * N_NODES)           // 500000
#define NSUP    (KTOT / 128)                // 11 super-chunks

// ---------------- device scratch ----------------
__device__ float g_h[2][(size_t)N_NODES * HIDDEN]; // ping-pong features
__device__ float g_Bw[(size_t)N_LAYERS * KTOT * HIDDEN]; // packed tf32 weights [l][k][n]
__device__ int   g_cntR[NRN];                      // per-(rel,dst) in-degree (r-major)
__device__ int   g_fillR[NRN];                     // fill cursors
__device__ int   g_off2[NRN + 1];                  // CSR offsets, edges sorted by (rel,dst)
__device__ int2  g_esd[N_EDGES];                   // per-edge (src, dst)
__device__ float g_ew[N_EDGES];                    // per-edge weight 1/cnt(dst,rel)

__device__ __forceinline__ float f2tf32(float f) {
    uint32_t r;
    asm("cvt.rna.tf32.f32 %0, %1;" : "=r"(r) : "f"(f));
    return __uint_as_float(r);
}

__device__ __forceinline__ void mma_tf32(float* c, const uint32_t* a, const uint32_t* b) {
    asm volatile(
        "mma.sync.aligned.m16n8k8.row.col.f32.tf32.tf32.f32 "
        "{%0,%1,%2,%3}, {%4,%5,%6,%7}, {%8,%9}, {%0,%1,%2,%3};"
        : "+f"(c[0]), "+f"(c[1]), "+f"(c[2]), "+f"(c[3])
        : "r"(a[0]), "r"(a[1]), "r"(a[2]), "r"(a[3]), "r"(b[0]), "r"(b[1]));
}

// ---------------- setup kernels (once per call) ----------------
__global__ void zero_cnt_kernel() {
    int i = blockIdx.x * blockDim.x + threadIdx.x;
    if (i < NRN) { g_cntR[i] = 0; g_fillR[i] = 0; }
}

__global__ void count_kernel(const int* __restrict__ ei, const int* __restrict__ et) {
    int e = blockIdx.x * blockDim.x + threadIdx.x;
    if (e >= N_EDGES) return;
    atomicAdd(&g_cntR[et[e] * N_NODES + ei[N_EDGES + e]], 1);
}

// single-block exclusive scan of g_cntR -> g_off2
__global__ void scan_kernel() {
    __shared__ int part[1024];
    int t = threadIdx.x;
    const int CH = (NRN + 1023) / 1024;   // 489
    int base = t * CH;
    int s = 0;
    for (int i = 0; i < CH; i++) {
        int idx = base + i;
        if (idx < NRN) s += g_cntR[idx];
    }
    part[t] = s;
    __syncthreads();
    for (int off = 1; off < 1024; off <<= 1) {
        int v = (t >= off) ? part[t - off] : 0;
        __syncthreads();
        part[t] += v;
        __syncthreads();
    }
    int run = (t > 0) ? part[t - 1] : 0;
    for (int i = 0; i < CH; i++) {
        int idx = base + i;
        if (idx < NRN) { g_off2[idx] = run; run += g_cntR[idx]; }
    }
    if (t == 1023) g_off2[NRN] = part[1023];
}

__global__ void fill_kernel(const int* __restrict__ ei, const int* __restrict__ et) {
    int e = blockIdx.x * blockDim.x + threadIdx.x;
    if (e >= N_EDGES) return;
    int src = ei[e];
    int dst = ei[N_EDGES + e];
    int r   = et[e];
    int slot = r * N_NODES + dst;
    int pos = g_off2[slot] + atomicAdd(&g_fillR[slot], 1);
    g_esd[pos] = make_int2(src, dst);
    g_ew[pos]  = 1.0f / (float)g_cntR[slot];
}

// pack all layers' weights: g_Bw[l][k][n]; k<128 root, else rel r=(k-128)/128
__global__ void bw_kernel(const float* __restrict__ rel_w, const float* __restrict__ root_w) {
    size_t idx = (size_t)blockIdx.x * blockDim.x + threadIdx.x;
    if (idx >= (size_t)N_LAYERS * KTOT * HIDDEN) return;
    int l = idx / (KTOT * HIDDEN);
    int rem = idx % (KTOT * HIDDEN);
    int k = rem / HIDDEN, n = rem % HIDDEN;
    float v;
    if (k < HIDDEN)
        v = root_w[(size_t)l * HIDDEN * HIDDEN + (size_t)k * HIDDEN + n];
    else
        v = rel_w[(size_t)l * N_REL * HIDDEN * HIDDEN + (size_t)(k - HIDDEN) * HIDDEN + n];
    g_Bw[idx] = f2tf32(v);
}

// ---------------- input projection ----------------
#define BM 64
#define BK 16
__global__ void proj_kernel(const float* __restrict__ x, const float* __restrict__ Wp,
                            const float* __restrict__ bp) {
    __shared__ float As[BK][BM + 4];
    __shared__ float Bs[BK][HIDDEN];
    int tid = threadIdx.x;
    int tm = tid >> 5, tn = tid & 31;
    int row0 = blockIdx.x * BM;
    float acc[8][4];
    #pragma unroll
    for (int i = 0; i < 8; i++)
        #pragma unroll
        for (int j = 0; j < 4; j++) acc[i][j] = 0.f;

    for (int k0 = 0; k0 < IN_DIM; k0 += BK) {
        {
            int r = tid >> 2, kc = (tid & 3) * 4, grow = row0 + r;
            float4 v = make_float4(0.f, 0.f, 0.f, 0.f);
            if (grow < N_NODES) v = *(const float4*)&x[(size_t)grow * IN_DIM + k0 + kc];
            As[kc + 0][r] = v.x; As[kc + 1][r] = v.y; As[kc + 2][r] = v.z; As[kc + 3][r] = v.w;
        }
        #pragma unroll
        for (int i = 0; i < 2; i++) {
            int f = tid + i * 256;
            int kk = f >> 5, c4 = (f & 31) * 4;
            *(float4*)&Bs[kk][c4] = *(const float4*)&Wp[(size_t)(k0 + kk) * HIDDEN + c4];
        }
        __syncthreads();
        #pragma unroll
        for (int kk = 0; kk < BK; kk++) {
            float a[8], b[4];
            *(float4*)&a[0] = *(const float4*)&As[kk][tm * 8];
            *(float4*)&a[4] = *(const float4*)&As[kk][tm * 8 + 4];
            *(float4*)&b[0] = *(const float4*)&Bs[kk][tn * 4];
            #pragma unroll
            for (int i = 0; i < 8; i++)
                #pragma unroll
                for (int j = 0; j < 4; j++) acc[i][j] = fmaf(a[i], b[j], acc[i][j]);
        }
        __syncthreads();
    }
    int n0 = tn * 4;
    float4 bb = *(const float4*)&bp[n0];
    #pragma unroll
    for (int i = 0; i < 8; i++) {
        int grow = row0 + tm * 8 + i;
        if (grow < N_NODES) {
            float4 o = make_float4(acc[i][0] + bb.x, acc[i][1] + bb.y,
                                   acc[i][2] + bb.z, acc[i][3] + bb.w);
            *(float4*)&g_h[0][(size_t)grow * HIDDEN + n0] = o;
        }
    }
}

// ---------------- fully fused layer kernel ----------------
// CTA: 64 dst rows x 128 out cols. K = 1408 as 11 super-chunks of 128.
//   sc=0: A = h[dst rows]        (root term)
//   sc=r+1: A[row] = sum_e w_e * h[src_e]  (CSR gather, warp owns 8 rows)
// Epilogue: +conv_b, LayerNorm, ReLU, +residual -> hnext.
#define AP 132
#define BP 136
#define SMEM_A 0
#define SMEM_B (64 * AP)                         // floats
#define SMEM_FLOATS (64 * AP + 128 * BP)         // 25856 floats = 103424 B

__global__ void __launch_bounds__(256, 2)
layer_kernel(const float* __restrict__ conv_b, const float* __restrict__ ln_g,
             const float* __restrict__ ln_b, int l, int cur) {
    extern __shared__ float smem[];
    float* As = smem + SMEM_A;       // [64][AP]
    float* Bs = smem + SMEM_B;       // [128][BP]
    const uint32_t* AsU = (const uint32_t*)As;
    const uint32_t* BsU = (const uint32_t*)Bs;

    int tid = threadIdx.x;
    int wid = tid >> 5;
    int lane = tid & 31;
    int gq = lane >> 2;              // 0..7
    int tq = lane & 3;               // 0..3
    int wm = (wid >> 1) * 16;        // warp M offset (4 warps in M)
    int wn = (wid & 1) * 64;         // warp N offset (2 warps in N)
    int row0 = blockIdx.x * 64;
    int wrow = wid * 8;              // warp's 8 A-build rows
    const float* hcur = g_h[cur];
    float* hnext = g_h[cur ^ 1];
    const float* Bw = g_Bw + (size_t)l * KTOT * HIDDEN;

    float c[8][4];
    #pragma unroll
    for (int nj = 0; nj < 8; nj++)
        #pragma unroll
        for (int q = 0; q < 4; q++) c[nj][q] = 0.f;

    for (int sc = 0; sc < NSUP; sc++) {
        __syncthreads();             // previous mma done; smem reusable
        // ---- load B super-chunk: 128 k-rows x 128 n ----
        {
            const float* Bsrc = Bw + (size_t)sc * 128 * HIDDEN;
            #pragma unroll
            for (int t = 0; t < 16; t++) {
                int idx = tid + t * 256;       // 0..4095 float4s
                int kk = idx >> 5, n4 = idx & 31;
                *(float4*)&Bs[kk * BP + n4 * 4] = *(const float4*)&Bsrc[(size_t)kk * HIDDEN + n4 * 4];
            }
        }
        // ---- build A (64 rows x 128 k) ----
        if (sc == 0) {
            #pragma unroll
            for (int i = 0; i < 8; i++) {
                int grow = row0 + wrow + i;
                float4 v = (grow < N_NODES)
                         ? *(const float4*)&hcur[(size_t)grow * HIDDEN + lane * 4]
                         : make_float4(0.f, 0.f, 0.f, 0.f);
                *(float4*)&As[(wrow + i) * AP + lane * 4] = v;
            }
        } else {
            int r = sc - 1;
            #pragma unroll
            for (int i = 0; i < 8; i++)
                *(float4*)&As[(wrow + i) * AP + lane * 4] = make_float4(0.f, 0.f, 0.f, 0.f);
            int d0 = row0 + wrow;     if (d0 > N_NODES) d0 = N_NODES;
            int d1 = row0 + wrow + 8; if (d1 > N_NODES) d1 = N_NODES;
            int lo = g_off2[r * N_NODES + d0];
            int hi = g_off2[r * N_NODES + d1];
            int e = lo;
            for (; e + 4 <= hi; e += 4) {
                int2 ea = g_esd[e], eb = g_esd[e + 1], ec = g_esd[e + 2], ed = g_esd[e + 3];
                float wa = g_ew[e], wb = g_ew[e + 1], wc = g_ew[e + 2], wd = g_ew[e + 3];
                float4 va = *(const float4*)&hcur[(size_t)ea.x * HIDDEN + lane * 4];
                float4 vb = *(const float4*)&hcur[(size_t)eb.x * HIDDEN + lane * 4];
                float4 vc = *(const float4*)&hcur[(size_t)ec.x * HIDDEN + lane * 4];
                float4 vd = *(const float4*)&hcur[(size_t)ed.x * HIDDEN + lane * 4];
                {
                    float4* p = (float4*)&As[(ea.y - row0) * AP + lane * 4];
                    float4 o = *p;
                    o.x = fmaf(va.x, wa, o.x); o.y = fmaf(va.y, wa, o.y);
                    o.z = fmaf(va.z, wa, o.z); o.w = fmaf(va.w, wa, o.w);
                    *p = o;
                }
                {
                    float4* p = (float4*)&As[(eb.y - row0) * AP + lane * 4];
                    float4 o = *p;
                    o.x = fmaf(vb.x, wb, o.x); o.y = fmaf(vb.y, wb, o.y);
                    o.z = fmaf(vb.z, wb, o.z); o.w = fmaf(vb.w, wb, o.w);
                    *p = o;
                }
                {
                    float4* p = (float4*)&As[(ec.y - row0) * AP + lane * 4];
                    float4 o = *p;
                    o.x = fmaf(vc.x, wc, o.x); o.y = fmaf(vc.y, wc, o.y);
                    o.z = fmaf(vc.z, wc, o.z); o.w = fmaf(vc.w, wc, o.w);
                    *p = o;
                }
                {
                    float4* p = (float4*)&As[(ed.y - row0) * AP + lane * 4];
                    float4 o = *p;
                    o.x = fmaf(vd.x, wd, o.x); o.y = fmaf(vd.y, wd, o.y);
                    o.z = fmaf(vd.z, wd, o.z); o.w = fmaf(vd.w, wd, o.w);
                    *p = o;
                }
            }
            for (; e < hi; e++) {
                int2 ee = g_esd[e];
                float w = g_ew[e];
                float4 v = *(const float4*)&hcur[(size_t)ee.x * HIDDEN + lane * 4];
                float4* p = (float4*)&As[(ee.y - row0) * AP + lane * 4];
                float4 o = *p;
                o.x = fmaf(v.x, w, o.x); o.y = fmaf(v.y, w, o.y);
                o.z = fmaf(v.z, w, o.z); o.w = fmaf(v.w, w, o.w);
                *p = o;
            }
        }
        __syncthreads();
        // ---- mma: 16 k-steps of 8 ----
        #pragma unroll
        for (int s = 0; s < 16; s++) {
            int kb = s * 8;
            uint32_t a[4], b[8][2];
            int rr = wm + gq;
            a[0] = AsU[rr * AP + kb + tq];
            a[1] = AsU[(rr + 8) * AP + kb + tq];
            a[2] = AsU[rr * AP + kb + tq + 4];
            a[3] = AsU[(rr + 8) * AP + kb + tq + 4];
            #pragma unroll
            for (int nj = 0; nj < 8; nj++) {
                int n = wn + nj * 8 + gq;
                b[nj][0] = BsU[(kb + tq) * BP + n];
                b[nj][1] = BsU[(kb + tq + 4) * BP + n];
            }
            #pragma unroll
            for (int nj = 0; nj < 8; nj++)
                mma_tf32(c[nj], a, b[nj]);
        }
    }

    // ---- epilogue: C -> smem, then LN + ReLU + residual ----
    __syncthreads();
    #pragma unroll
    for (int nj = 0; nj < 8; nj++) {
        int cb = wn + nj * 8 + 2 * tq;
        int r0 = wm + gq, r1 = r0 + 8;
        As[r0 * AP + cb]     = c[nj][0];
        As[r0 * AP + cb + 1] = c[nj][1];
        As[r1 * AP + cb]     = c[nj][2];
        As[r1 * AP + cb + 1] = c[nj][3];
    }
    __syncthreads();

    int n0 = lane * 4;
    float4 cb4 = *(const float4*)&conv_b[l * HIDDEN + n0];
    float4 g4  = *(const float4*)&ln_g[l * HIDDEN + n0];
    float4 b4  = *(const float4*)&ln_b[l * HIDDEN + n0];
    #pragma unroll
    for (int i = 0; i < 8; i++) {
        int lrow = wid * 8 + i;
        int row = row0 + lrow;
        if (row >= N_NODES) break;
        float4 v = *(const float4*)&As[lrow * AP + n0];
        v.x += cb4.x; v.y += cb4.y; v.z += cb4.z; v.w += cb4.w;
        float sm = v.x + v.y + v.z + v.w;
        float q = v.x * v.x + v.y * v.y + v.z * v.z + v.w * v.w;
        #pragma unroll
        for (int o = 16; o > 0; o >>= 1) {
            sm += __shfl_xor_sync(0xFFFFFFFFu, sm, o);
            q  += __shfl_xor_sync(0xFFFFFFFFu, q, o);
        }
        float mu = sm * (1.0f / HIDDEN);
        float var = q * (1.0f / HIDDEN) - mu * mu;
        float rs = rsqrtf(var + LN_EPS);
        float4 rv = *(const float4*)&hcur[(size_t)row * HIDDEN + n0];
        float4 o;
        o.x = fmaxf((v.x - mu) * rs * g4.x + b4.x, 0.f) + rv.x;
        o.y = fmaxf((v.y - mu) * rs * g4.y + b4.y, 0.f) + rv.y;
        o.z = fmaxf((v.z - mu) * rs * g4.z + b4.z, 0.f) + rv.z;
        o.w = fmaxf((v.w - mu) * rs * g4.w + b4.w, 0.f) + rv.w;
        *(float4*)&hnext[(size_t)row * HIDDEN + n0] = o;
    }
}

// ---------------- pooling ----------------
__device__ __forceinline__ int lower_bound_dev(const int* __restrict__ a, int n, int v) {
    int lo = 0, hi = n;
    while (lo < hi) { int mid = (lo + hi) >> 1; if (a[mid] < v) lo = mid + 1; else hi = mid; }
    return lo;
}

__global__ void pool_kernel(const int* __restrict__ batch, float* __restrict__ out, int finalbuf) {
    int g = blockIdx.x;
    int tid = threadIdx.x;
    int start = lower_bound_dev(batch, N_NODES, g);
    int end   = lower_bound_dev(batch, N_NODES, g + 1);
    const float* h = g_h[finalbuf];
    float acc = 0.f;
    for (int i = start; i < end; i++)
        acc += h[(size_t)i * HIDDEN + tid];
    out[g * HIDDEN + tid] = acc;
}

// ---------------- launch ----------------
extern "C" void kernel_launch(void* const* d_in, const int* in_sizes, int n_in,
                              void* d_out, int out_size) {
    const float* x      = (const float*)d_in[0];
    const int* ei       = (const int*)d_in[1];
    const int* et       = (const int*)d_in[2];
    const int* batch    = (const int*)d_in[3];
    const float* Wp     = (const float*)d_in[4];
    const float* bp     = (const float*)d_in[5];
    const float* rel_w  = (const float*)d_in[6];
    const float* root_w = (const float*)d_in[7];
    const float* conv_b = (const float*)d_in[8];
    const float* ln_g   = (const float*)d_in[9];
    const float* ln_b   = (const float*)d_in[10];
    float* out = (float*)d_out;

    cudaFuncSetAttribute(layer_kernel, cudaFuncAttributeMaxDynamicSharedMemorySize,
                         SMEM_FLOATS * (int)sizeof(float));

    // CSR by (rel, dst) — structure only
    zero_cnt_kernel<<<(NRN + 255) / 256, 256>>>();
    count_kernel<<<(N_EDGES + 255) / 256, 256>>>(ei, et);
    scan_kernel<<<1, 1024>>>();
    fill_kernel<<<(N_EDGES + 255) / 256, 256>>>(ei, et);

    // weights packed once for all layers
    bw_kernel<<<(int)(((size_t)N_LAYERS * KTOT * HIDDEN + 255) / 256), 256>>>(rel_w, root_w);

    proj_kernel<<<(N_NODES + BM - 1) / BM, 256>>>(x, Wp, bp);

    int nblk = (N_NODES + 63) / 64;
    for (int l = 0; l < N_LAYERS; l++) {
        layer_kernel<<<nblk, 256, SMEM_FLOATS * (int)sizeof(float)>>>(
            conv_b, ln_g, ln_b, l, l & 1);
    }

    pool_kernel<<<N_GRAPHS, HIDDEN>>>(batch, out, 0);
}

// round 10
// speedup vs baseline: 1.0382x; 1.0382x over previous
#include <cuda_runtime.h>
#include <cuda_fp16.h>
#include <cstdint>

#define N_NODES 50000
#define N_EDGES 600000
#define IN_DIM  64
#define HIDDEN  128
#define N_REL   10
#define N_LAYERS 6
#define N_GRAPHS 64
#define LN_EPS  1e-5f

#define KN      (HIDDEN + N_REL * HIDDEN)   // 1408 Y columns = [root | rel0..rel9]
#define KNH     (KN / 2)                    // 704 uint32 (fp16x2) per Y row

// ---------------- device scratch ----------------
__device__ uint32_t g_Yh[(size_t)N_NODES * KNH];   // transformed features, fp16, 140.8 MB
__device__ float g_h[2][(size_t)N_NODES * HIDDEN]; // ping-pong features (fp32)
__device__ float g_Bw[(size_t)N_LAYERS * HIDDEN * KN]; // packed tf32 weights [l][k][n]
__device__ int   g_cnt[N_NODES * N_REL];           // per-(dst,rel) in-degree
__device__ int   g_cntd[N_NODES];                  // per-dst in-degree
__device__ int   g_start[N_NODES];                 // CSR offsets (by dst)
__device__ int   g_fill[N_NODES];                  // CSR fill cursors
__device__ int   g_coff[N_EDGES];                  // per-edge src offset into g_Yh (u32 units)
__device__ float g_cw[N_EDGES];                    // per-edge weight 1/cnt(dst,rel)

__device__ __forceinline__ float f2tf32(float f) {
    uint32_t r;
    asm("cvt.rna.tf32.f32 %0, %1;" : "=r"(r) : "f"(f));
    return __uint_as_float(r);
}

__device__ __forceinline__ uint32_t pack_h2(float lo, float hi) {
    __half2 h = __floats2half2_rn(lo, hi);
    return *(uint32_t*)&h;
}

__device__ __forceinline__ void mma_tf32(float* c, const uint32_t* a, const uint32_t* b) {
    asm volatile(
        "mma.sync.aligned.m16n8k8.row.col.f32.tf32.tf32.f32 "
        "{%0,%1,%2,%3}, {%4,%5,%6,%7}, {%8,%9}, {%0,%1,%2,%3};"
        : "+f"(c[0]), "+f"(c[1]), "+f"(c[2]), "+f"(c[3])
        : "r"(a[0]), "r"(a[1]), "r"(a[2]), "r"(a[3]), "r"(b[0]), "r"(b[1]));
}

// ---------------- setup kernels (once per call) ----------------
__global__ void zero_cnt_kernel() {
    int i = blockIdx.x * blockDim.x + threadIdx.x;
    if (i < N_NODES * N_REL) g_cnt[i] = 0;
    if (i < N_NODES) { g_cntd[i] = 0; g_fill[i] = 0; }
}

__global__ void count_kernel(const int* __restrict__ ei, const int* __restrict__ et) {
    int e = blockIdx.x * blockDim.x + threadIdx.x;
    if (e >= N_EDGES) return;
    int dst = ei[N_EDGES + e];
    atomicAdd(&g_cnt[dst * N_REL + et[e]], 1);
    atomicAdd(&g_cntd[dst], 1);
}

// single-block exclusive scan of g_cntd -> g_start
__global__ void scan_kernel() {
    __shared__ int part[1024];
    int t = threadIdx.x;
    const int CH = (N_NODES + 1023) / 1024;
    int base = t * CH;
    int s = 0;
    for (int i = 0; i < CH; i++) {
        int idx = base + i;
        if (idx < N_NODES) s += g_cntd[idx];
    }
    part[t] = s;
    __syncthreads();
    for (int off = 1; off < 1024; off <<= 1) {
        int v = (t >= off) ? part[t - off] : 0;
        __syncthreads();
        part[t] += v;
        __syncthreads();
    }
    int run = (t > 0) ? part[t - 1] : 0;
    for (int i = 0; i < CH; i++) {
        int idx = base + i;
        if (idx < N_NODES) { g_start[idx] = run; run += g_cntd[idx]; }
    }
}

__global__ void fill_kernel(const int* __restrict__ ei, const int* __restrict__ et) {
    int e = blockIdx.x * blockDim.x + threadIdx.x;
    if (e >= N_EDGES) return;
    int src = ei[e];
    int dst = ei[N_EDGES + e];
    int r   = et[e];
    int pos = g_start[dst] + atomicAdd(&g_fill[dst], 1);
    g_coff[pos] = src * KNH + (HIDDEN / 2) + r * (HIDDEN / 2);  // u32 units
    g_cw[pos]   = 1.0f / (float)g_cnt[dst * N_REL + r];
}

// pack all layers' weights: g_Bw[l][k][n], n<128 -> root, else rel r=(n-128)/128
__global__ void bw_kernel(const float* __restrict__ rel_w, const float* __restrict__ root_w) {
    size_t idx = (size_t)blockIdx.x * blockDim.x + threadIdx.x;
    if (idx >= (size_t)N_LAYERS * HIDDEN * KN) return;
    int l = idx / (HIDDEN * KN);
    int rem = idx % (HIDDEN * KN);
    int k = rem / KN, n = rem % KN;
    float v;
    if (n < HIDDEN)
        v = root_w[(size_t)l * HIDDEN * HIDDEN + (size_t)k * HIDDEN + n];
    else {
        int r = (n - HIDDEN) / HIDDEN, j = (n - HIDDEN) % HIDDEN;
        v = rel_w[(size_t)l * N_REL * HIDDEN * HIDDEN + (size_t)r * HIDDEN * HIDDEN
                  + (size_t)k * HIDDEN + j];
    }
    g_Bw[idx] = f2tf32(v);
}

// ---------------- input projection ----------------
#define BM 64
#define BK 16
__global__ void proj_kernel(const float* __restrict__ x, const float* __restrict__ Wp,
                            const float* __restrict__ bp) {
    __shared__ float As[BK][BM + 4];
    __shared__ float Bs[BK][HIDDEN];
    int tid = threadIdx.x;
    int tm = tid >> 5, tn = tid & 31;
    int row0 = blockIdx.x * BM;
    float acc[8][4];
    #pragma unroll
    for (int i = 0; i < 8; i++)
        #pragma unroll
        for (int j = 0; j < 4; j++) acc[i][j] = 0.f;

    for (int k0 = 0; k0 < IN_DIM; k0 += BK) {
        {
            int r = tid >> 2, kc = (tid & 3) * 4, grow = row0 + r;
            float4 v = make_float4(0.f, 0.f, 0.f, 0.f);
            if (grow < N_NODES) v = *(const float4*)&x[(size_t)grow * IN_DIM + k0 + kc];
            As[kc + 0][r] = v.x; As[kc + 1][r] = v.y; As[kc + 2][r] = v.z; As[kc + 3][r] = v.w;
        }
        #pragma unroll
        for (int i = 0; i < 2; i++) {
            int f = tid + i * 256;
            int kk = f >> 5, c4 = (f & 31) * 4;
            *(float4*)&Bs[kk][c4] = *(const float4*)&Wp[(size_t)(k0 + kk) * HIDDEN + c4];
        }
        __syncthreads();
        #pragma unroll
        for (int kk = 0; kk < BK; kk++) {
            float a[8], b[4];
            *(float4*)&a[0] = *(const float4*)&As[kk][tm * 8];
            *(float4*)&a[4] = *(const float4*)&As[kk][tm * 8 + 4];
            *(float4*)&b[0] = *(const float4*)&Bs[kk][tn * 4];
            #pragma unroll
            for (int i = 0; i < 8; i++)
                #pragma unroll
                for (int j = 0; j < 4; j++) acc[i][j] = fmaf(a[i], b[j], acc[i][j]);
        }
        __syncthreads();
    }
    int n0 = tn * 4;
    float4 bb = *(const float4*)&bp[n0];
    #pragma unroll
    for (int i = 0; i < 8; i++) {
        int grow = row0 + tm * 8 + i;
        if (grow < N_NODES) {
            float4 o = make_float4(acc[i][0] + bb.x, acc[i][1] + bb.y,
                                   acc[i][2] + bb.z, acc[i][3] + bb.w);
            *(float4*)&g_h[0][(size_t)grow * HIDDEN + n0] = o;
        }
    }
}

// ---------------- tf32 GEMM: g_Yh = fp16(h @ W_all)   (M=50000, K=128, N=1408) ----------------
#define APITCH 36
#define BPITCH 136

__global__ void __launch_bounds__(256, 2)
gemm_mma_kernel(int cur, int l) {
    __shared__ float As[128 * APITCH];
    __shared__ float Bs[32 * BPITCH];

    int tid = threadIdx.x;
    int wid = tid >> 5;
    int lane = tid & 31;
    int gq = lane >> 2;
    int tq = lane & 3;
    int wm = (wid >> 1) * 32;
    int wn = (wid & 1) * 64;
    int row0 = blockIdx.y * 128;
    int ncol0 = blockIdx.x * 128;
    const float* hcur = g_h[cur];
    const float* Bw = g_Bw + (size_t)l * HIDDEN * KN;

    float c[2][8][4];
    #pragma unroll
    for (int mi = 0; mi < 2; mi++)
        #pragma unroll
        for (int nj = 0; nj < 8; nj++)
            #pragma unroll
            for (int q = 0; q < 4; q++) c[mi][nj][q] = 0.f;

    const uint32_t* AsU = (const uint32_t*)As;
    const uint32_t* BsU = (const uint32_t*)Bs;

    #pragma unroll
    for (int i = 0; i < 4; i++) {
        int k0 = i * 32;
        float4 av[4], bv[4];
        #pragma unroll
        for (int t = 0; t < 4; t++) {
            int idx = tid + t * 256;
            int r = idx >> 3, cc = idx & 7;
            int grow = row0 + r;
            av[t] = (grow < N_NODES)
                  ? *(const float4*)&hcur[(size_t)grow * HIDDEN + k0 + cc * 4]
                  : make_float4(0.f, 0.f, 0.f, 0.f);
        }
        #pragma unroll
        for (int t = 0; t < 4; t++) {
            int idx = tid + t * 256;
            int kk = idx >> 5, n4 = idx & 31;
            bv[t] = *(const float4*)&Bw[(size_t)(k0 + kk) * KN + ncol0 + n4 * 4];
        }
        __syncthreads();
        #pragma unroll
        for (int t = 0; t < 4; t++) {
            int idx = tid + t * 256;
            int r = idx >> 3, cc = idx & 7;
            float4 cv = make_float4(f2tf32(av[t].x), f2tf32(av[t].y),
                                    f2tf32(av[t].z), f2tf32(av[t].w));
            *(float4*)&As[r * APITCH + cc * 4] = cv;
        }
        #pragma unroll
        for (int t = 0; t < 4; t++) {
            int idx = tid + t * 256;
            int kk = idx >> 5, n4 = idx & 31;
            *(float4*)&Bs[kk * BPITCH + n4 * 4] = bv[t];
        }
        __syncthreads();

        #pragma unroll
        for (int s = 0; s < 4; s++) {
            int kb = s * 8;
            uint32_t a[2][4], b[8][2];
            #pragma unroll
            for (int mi = 0; mi < 2; mi++) {
                int r = wm + mi * 16 + gq;
                a[mi][0] = AsU[r * APITCH + kb + tq];
                a[mi][1] = AsU[(r + 8) * APITCH + kb + tq];
                a[mi][2] = AsU[r * APITCH + kb + tq + 4];
                a[mi][3] = AsU[(r + 8) * APITCH + kb + tq + 4];
            }
            #pragma unroll
            for (int nj = 0; nj < 8; nj++) {
                int n = wn + nj * 8 + gq;
                b[nj][0] = BsU[(kb + tq) * BPITCH + n];
                b[nj][1] = BsU[(kb + tq + 4) * BPITCH + n];
            }
            #pragma unroll
            for (int mi = 0; mi < 2; mi++)
                #pragma unroll
                for (int nj = 0; nj < 8; nj++)
                    mma_tf32(c[mi][nj], a[mi], b[nj]);
        }
        __syncthreads();
    }

    // store C to g_Yh (fp16x2 per u32)
    #pragma unroll
    for (int mi = 0; mi < 2; mi++) {
        int r0 = row0 + wm + mi * 16 + gq;
        #pragma unroll
        for (int nj = 0; nj < 8; nj++) {
            int cb = ncol0 + wn + nj * 8 + 2 * tq;     // even
            if (r0 < N_NODES)
                g_Yh[(size_t)r0 * KNH + (cb >> 1)] = pack_h2(c[mi][nj][0], c[mi][nj][1]);
            if (r0 + 8 < N_NODES)
                g_Yh[(size_t)(r0 + 8) * KNH + (cb >> 1)] = pack_h2(c[mi][nj][2], c[mi][nj][3]);
        }
    }
}

// ---------------- fused CSR gather + bias + LN + ReLU + residual ----------------
// warp per dst node: acc = Y[dst, 0:128] + conv_b + sum_e w_e * Y[coff_e : +128]
__device__ __forceinline__ void fma_h2(float4& acc, uint2 v, float w) {
    float2 a = __half22float2(*(__half2*)&v.x);
    float2 b = __half22float2(*(__half2*)&v.y);
    acc.x = fmaf(a.x, w, acc.x);
    acc.y = fmaf(a.y, w, acc.y);
    acc.z = fmaf(b.x, w, acc.z);
    acc.w = fmaf(b.y, w, acc.w);
}

__global__ void gather_ln_kernel(const float* __restrict__ conv_b, const float* __restrict__ ln_g,
                                 const float* __restrict__ ln_b, int l, int cur) {
    int wid = threadIdx.x >> 5;
    int lane = threadIdx.x & 31;
    int row = blockIdx.x * 8 + wid;
    if (row >= N_NODES) return;
    int n0 = lane * 4;
    int lo2 = lane * 2;                  // u32 offset within a 128-col block
    const float* hcur = g_h[cur];
    float* hnext = g_h[cur ^ 1];

    float4 acc;
    {
        uint2 rv = *(const uint2*)&g_Yh[(size_t)row * KNH + lo2];
        float2 a = __half22float2(*(__half2*)&rv.x);
        float2 b = __half22float2(*(__half2*)&rv.y);
        float4 cb = *(const float4*)&conv_b[l * HIDDEN + n0];
        acc.x = a.x + cb.x; acc.y = a.y + cb.y; acc.z = b.x + cb.z; acc.w = b.y + cb.w;
    }

    int s = g_start[row];
    int e = s + g_cntd[row];
    int i = s;
    for (; i + 4 <= e; i += 4) {
        int o0 = g_coff[i],     o1 = g_coff[i + 1];
        int o2 = g_coff[i + 2], o3 = g_coff[i + 3];
        float w0 = g_cw[i],     w1 = g_cw[i + 1];
        float w2 = g_cw[i + 2], w3 = g_cw[i + 3];
        uint2 v0 = *(const uint2*)&g_Yh[(size_t)o0 + lo2];
        uint2 v1 = *(const uint2*)&g_Yh[(size_t)o1 + lo2];
        uint2 v2 = *(const uint2*)&g_Yh[(size_t)o2 + lo2];
        uint2 v3 = *(const uint2*)&g_Yh[(size_t)o3 + lo2];
        fma_h2(acc, v0, w0);
        fma_h2(acc, v1, w1);
        fma_h2(acc, v2, w2);
        fma_h2(acc, v3, w3);
    }
    for (; i < e; i++) {
        uint2 v = *(const uint2*)&g_Yh[(size_t)g_coff[i] + lo2];
        fma_h2(acc, v, g_cw[i]);
    }

    float sm = acc.x + acc.y + acc.z + acc.w;
    float q = acc.x * acc.x + acc.y * acc.y + acc.z * acc.z + acc.w * acc.w;
    #pragma unroll
    for (int o = 16; o > 0; o >>= 1) {
        sm += __shfl_xor_sync(0xFFFFFFFFu, sm, o);
        q  += __shfl_xor_sync(0xFFFFFFFFu, q, o);
    }
    float mu = sm * (1.0f / HIDDEN);
    float var = q * (1.0f / HIDDEN) - mu * mu;
    float rs = rsqrtf(var + LN_EPS);
    float4 g4 = *(const float4*)&ln_g[l * HIDDEN + n0];
    float4 b4 = *(const float4*)&ln_b[l * HIDDEN + n0];
    float4 rv = *(const float4*)&hcur[(size_t)row * HIDDEN + n0];
    float4 o;
    o.x = fmaxf((acc.x - mu) * rs * g4.x + b4.x, 0.f) + rv.x;
    o.y = fmaxf((acc.y - mu) * rs * g4.y + b4.y, 0.f) + rv.y;
    o.z = fmaxf((acc.z - mu) * rs * g4.z + b4.z, 0.f) + rv.z;
    o.w = fmaxf((acc.w - mu) * rs * g4.w + b4.w, 0.f) + rv.w;
    *(float4*)&hnext[(size_t)row * HIDDEN + n0] = o;
}

// ---------------- pooling ----------------
__device__ __forceinline__ int lower_bound_dev(const int* __restrict__ a, int n, int v) {
    int lo = 0, hi = n;
    while (lo < hi) { int mid = (lo + hi) >> 1; if (a[mid] < v) lo = mid + 1; else hi = mid; }
    return lo;
}

__global__ void pool_kernel(const int* __restrict__ batch, float* __restrict__ out, int finalbuf) {
    int g = blockIdx.x;
    int tid = threadIdx.x;
    int start = lower_bound_dev(batch, N_NODES, g);
    int end   = lower_bound_dev(batch, N_NODES, g + 1);
    const float* h = g_h[finalbuf];
    float acc = 0.f;
    for (int i = start; i < end; i++)
        acc += h[(size_t)i * HIDDEN + tid];
    out[g * HIDDEN + tid] = acc;
}

// ---------------- launch ----------------
extern "C" void kernel_launch(void* const* d_in, const int* in_sizes, int n_in,
                              void* d_out, int out_size) {
    const float* x      = (const float*)d_in[0];
    const int* ei       = (const int*)d_in[1];
    const int* et       = (const int*)d_in[2];
    const int* batch    = (const int*)d_in[3];
    const float* Wp     = (const float*)d_in[4];
    const float* bp     = (const float*)d_in[5];
    const float* rel_w  = (const float*)d_in[6];
    const float* root_w = (const float*)d_in[7];
    const float* conv_b = (const float*)d_in[8];
    const float* ln_g   = (const float*)d_in[9];
    const float* ln_b   = (const float*)d_in[10];
    float* out = (float*)d_out;

    // CSR + counts (structure only)
    zero_cnt_kernel<<<(N_NODES * N_REL + 255) / 256, 256>>>();
    count_kernel<<<(N_EDGES + 255) / 256, 256>>>(ei, et);
    scan_kernel<<<1, 1024>>>();
    fill_kernel<<<(N_EDGES + 255) / 256, 256>>>(ei, et);

    // weights packed once for all layers
    bw_kernel<<<(int)(((size_t)N_LAYERS * HIDDEN * KN + 255) / 256), 256>>>(rel_w, root_w);

    proj_kernel<<<(N_NODES + BM - 1) / BM, 256>>>(x, Wp, bp);

    dim3 ggrid(KN / 128, (N_NODES + 127) / 128);
    for (int l = 0; l < N_LAYERS; l++) {
        int cur = l & 1;
        gemm_mma_kernel<<<ggrid, 256>>>(cur, l);
        gather_ln_kernel<<<(N_NODES + 7) / 8, 256>>>(conv_b, ln_g, ln_b, l, cur);
    }

    pool_kernel<<<N_GRAPHS, HIDDEN>>>(batch, out, 0);
}

// round 12
// speedup vs baseline: 1.3355x; 1.2864x over previous
#include <cuda_runtime.h>
#include <cuda_fp16.h>
#include <cstdint>

#define N_NODES 50000
#define N_EDGES 600000
#define IN_DIM  64
#define HIDDEN  128
#define N_REL   10
#define N_LAYERS 6
#define N_GRAPHS 64
#define LN_EPS  1e-5f

#define NRN     (N_REL * N_NODES)          // 500000 (rel,src) slots
#define ROOTPAD 50048                      // pad128(50000)
#define NJMAX   (ROOTPAD * 11)             // worst-case padded job rows = 550528
#define MAXTILES (NJMAX / 128)             // 4301

// ---------------- device scratch ----------------
__device__ uint32_t g_Yc[(size_t)NJMAX * 64];      // compact Y, fp16x2 per u32 (<=141MB)
__device__ float g_h[2][(size_t)N_NODES * HIDDEN]; // ping-pong features (fp32)
__device__ float g_Bw[(size_t)N_LAYERS * 11 * 128 * 128]; // packed tf32 weights [l][rr][k][n]
__device__ int   g_cnt[N_NODES * N_REL];           // in-degree per (dst,rel) -> mean weight
__device__ int   g_cntSR[NRN];                     // out-degree per (rel,src) -> compaction
__device__ int   g_cntd[N_NODES];                  // per-dst in-degree
__device__ int   g_start[N_NODES];                 // CSR offsets (by dst)
__device__ int   g_fill[N_NODES];                  // CSR fill cursors
__device__ int   g_jobrank[NRN];                   // global rank among flagged slots
__device__ int   g_cumRel[N_REL + 1];              // flagged count before each rel
__device__ int   g_jb[12];                         // job base per region (0=root), [11]=total
__device__ int   g_joblist[NJMAX];                 // job row -> src node
__device__ int   g_jobidx[NRN];                    // (rel,src) -> u32 offset into g_Yc
__device__ int   g_coff[N_EDGES];                  // per-edge u32 offset into g_Yc
__device__ float g_cw[N_EDGES];                    // per-edge weight 1/cnt(dst,rel)

__device__ __forceinline__ float f2tf32(float f) {
    uint32_t r;
    asm("cvt.rna.tf32.f32 %0, %1;" : "=r"(r) : "f"(f));
    return __uint_as_float(r);
}

__device__ __forceinline__ uint32_t pack_h2(float lo, float hi) {
    __half2 h = __floats2half2_rn(lo, hi);
    return *(uint32_t*)&h;
}

__device__ __forceinline__ void mma_tf32(float* c, const uint32_t* a, const uint32_t* b) {
    asm volatile(
        "mma.sync.aligned.m16n8k8.row.col.f32.tf32.tf32.f32 "
        "{%0,%1,%2,%3}, {%4,%5,%6,%7}, {%8,%9}, {%0,%1,%2,%3};"
        : "+f"(c[0]), "+f"(c[1]), "+f"(c[2]), "+f"(c[3])
        : "r"(a[0]), "r"(a[1]), "r"(a[2]), "r"(a[3]), "r"(b[0]), "r"(b[1]));
}

// ---------------- setup kernels (once per call) ----------------
__global__ void init_kernel() {
    int i = blockIdx.x * blockDim.x + threadIdx.x;
    if (i < NRN) { g_cntSR[i] = 0; }
    if (i < N_NODES * N_REL) g_cnt[i] = 0;
    if (i < N_NODES) { g_cntd[i] = 0; g_fill[i] = 0; }
}

__global__ void count_kernel(const int* __restrict__ ei, const int* __restrict__ et) {
    int e = blockIdx.x * blockDim.x + threadIdx.x;
    if (e >= N_EDGES) return;
    int src = ei[e];
    int dst = ei[N_EDGES + e];
    int r = et[e];
    atomicAdd(&g_cnt[dst * N_REL + r], 1);
    atomicAdd(&g_cntSR[r * N_NODES + src], 1);
    atomicAdd(&g_cntd[dst], 1);
}

// single-block exclusive scan of g_cntd -> g_start
__global__ void scan_dst_kernel() {
    __shared__ int part[1024];
    int t = threadIdx.x;
    const int CH = (N_NODES + 1023) / 1024;
    int base = t * CH;
    int s = 0;
    for (int i = 0; i < CH; i++) {
        int idx = base + i;
        if (idx < N_NODES) s += g_cntd[idx];
    }
    part[t] = s;
    __syncthreads();
    for (int off = 1; off < 1024; off <<= 1) {
        int v = (t >= off) ? part[t - off] : 0;
        __syncthreads();
        part[t] += v;
        __syncthreads();
    }
    int run = (t > 0) ? part[t - 1] : 0;
    for (int i = 0; i < CH; i++) {
        int idx = base + i;
        if (idx < N_NODES) { g_start[idx] = run; run += g_cntd[idx]; }
    }
}

// single-block scan over (rel,src) flags -> ranks, per-rel cum counts, job bases
__global__ void scanSR_kernel() {
    __shared__ int part[1024];
    int t = threadIdx.x;
    const int CH = (NRN + 1023) / 1024;   // 489
    int base = t * CH;
    int s = 0;
    for (int i = 0; i < CH; i++) {
        int idx = base + i;
        if (idx < NRN && g_cntSR[idx] > 0) s++;
    }
    part[t] = s;
    __syncthreads();
    for (int off = 1; off < 1024; off <<= 1) {
        int v = (t >= off) ? part[t - off] : 0;
        __syncthreads();
        part[t] += v;
        __syncthreads();
    }
    int run = (t > 0) ? part[t - 1] : 0;
    for (int i = 0; i < CH; i++) {
        int idx = base + i;
        if (idx >= NRN) break;
        if (idx % N_NODES == 0) g_cumRel[idx / N_NODES] = run;
        if (g_cntSR[idx] > 0) { g_jobrank[idx] = run; run++; }
    }
    if (t == 1023) g_cumRel[N_REL] = part[1023];
    __syncthreads();
    if (t == 0) {
        g_jb[0] = 0;
        int b = ROOTPAD;
        for (int r = 0; r < N_REL; r++) {
            g_jb[1 + r] = b;
            int c = g_cumRel[r + 1] - g_cumRel[r];
            b += (c + 127) & ~127;
        }
        g_jb[11] = b;
    }
}

__global__ void jobinit_kernel() {
    int i = blockIdx.x * blockDim.x + threadIdx.x;
    if (i < NJMAX) g_joblist[i] = (i < N_NODES) ? i : 0;
}

__global__ void jobbuild_kernel() {
    int i = blockIdx.x * blockDim.x + threadIdx.x;
    if (i >= NRN) return;
    if (g_cntSR[i] > 0) {
        int r = i / N_NODES, src = i % N_NODES;
        int idx = g_jb[1 + r] + (g_jobrank[i] - g_cumRel[r]);
        g_joblist[idx] = src;
        g_jobidx[i] = idx * 64;        // u32 offset, premultiplied
    }
}

__global__ void fill_kernel(const int* __restrict__ ei, const int* __restrict__ et) {
    int e = blockIdx.x * blockDim.x + threadIdx.x;
    if (e >= N_EDGES) return;
    int src = ei[e];
    int dst = ei[N_EDGES + e];
    int r   = et[e];
    int pos = g_start[dst] + atomicAdd(&g_fill[dst], 1);
    g_coff[pos] = g_jobidx[r * N_NODES + src];
    g_cw[pos]   = 1.0f / (float)g_cnt[dst * N_REL + r];
}

// pack weights: g_Bw[l][rr][k][n], rr=0 root, rr=1+r rel r (tf32-rounded)
__global__ void bw_kernel(const float* __restrict__ rel_w, const float* __restrict__ root_w) {
    size_t idx = (size_t)blockIdx.x * blockDim.x + threadIdx.x;
    if (idx >= (size_t)N_LAYERS * 11 * 16384) return;
    int l = idx / (11 * 16384);
    int rem = idx % (11 * 16384);
    int rr = rem / 16384;
    int k = (rem % 16384) / 128, n = rem % 128;
    float v;
    if (rr == 0)
        v = root_w[(size_t)l * 16384 + k * 128 + n];
    else
        v = rel_w[(size_t)l * N_REL * 16384 + (size_t)(rr - 1) * 16384 + k * 128 + n];
    g_Bw[idx] = f2tf32(v);
}

// ---------------- input projection ----------------
#define BM 64
#define BK 16
__global__ void proj_kernel(const float* __restrict__ x, const float* __restrict__ Wp,
                            const float* __restrict__ bp) {
    __shared__ float As[BK][BM + 4];
    __shared__ float Bs[BK][HIDDEN];
    int tid = threadIdx.x;
    int tm = tid >> 5, tn = tid & 31;
    int row0 = blockIdx.x * BM;
    float acc[8][4];
    #pragma unroll
    for (int i = 0; i < 8; i++)
        #pragma unroll
        for (int j = 0; j < 4; j++) acc[i][j] = 0.f;

    for (int k0 = 0; k0 < IN_DIM; k0 += BK) {
        {
            int r = tid >> 2, kc = (tid & 3) * 4, grow = row0 + r;
            float4 v = make_float4(0.f, 0.f, 0.f, 0.f);
            if (grow < N_NODES) v = *(const float4*)&x[(size_t)grow * IN_DIM + k0 + kc];
            As[kc + 0][r] = v.x; As[kc + 1][r] = v.y; As[kc + 2][r] = v.z; As[kc + 3][r] = v.w;
        }
        #pragma unroll
        for (int i = 0; i < 2; i++) {
            int f = tid + i * 256;
            int kk = f >> 5, c4 = (f & 31) * 4;
            *(float4*)&Bs[kk][c4] = *(const float4*)&Wp[(size_t)(k0 + kk) * HIDDEN + c4];
        }
        __syncthreads();
        #pragma unroll
        for (int kk = 0; kk < BK; kk++) {
            float a[8], b[4];
            *(float4*)&a[0] = *(const float4*)&As[kk][tm * 8];
            *(float4*)&a[4] = *(const float4*)&As[kk][tm * 8 + 4];
            *(float4*)&b[0] = *(const float4*)&Bs[kk][tn * 4];
            #pragma unroll
            for (int i = 0; i < 8; i++)
                #pragma unroll
                for (int j = 0; j < 4; j++) acc[i][j] = fmaf(a[i], b[j], acc[i][j]);
        }
        __syncthreads();
    }
    int n0 = tn * 4;
    float4 bb = *(const float4*)&bp[n0];
    #pragma unroll
    for (int i = 0; i < 8; i++) {
        int grow = row0 + tm * 8 + i;
        if (grow < N_NODES) {
            float4 o = make_float4(acc[i][0] + bb.x, acc[i][1] + bb.y,
                                   acc[i][2] + bb.z, acc[i][3] + bb.w);
            *(float4*)&g_h[0][(size_t)grow * HIDDEN + n0] = o;
        }
    }
}

// ---------------- compacted tf32 GEMM: g_Yc[job] = fp16(h[joblist[job]] @ W[rel(job)]) ----------------
#define APITCH 36
#define BPITCH 136

__global__ void __launch_bounds__(256, 2)
gemmc_kernel(int cur, int l) {
    __shared__ float As[128 * APITCH];
    __shared__ float Bs[32 * BPITCH];
    __shared__ int rows[128];

    int jobs0 = blockIdx.x * 128;
    if (jobs0 >= g_jb[11]) return;
    int rr = 0;
    #pragma unroll
    for (int r = 1; r < 11; r++)
        if (jobs0 >= g_jb[r]) rr = r;

    int tid = threadIdx.x;
    int wid = tid >> 5;
    int lane = tid & 31;
    int gq = lane >> 2;
    int tq = lane & 3;
    int wm = (wid >> 1) * 32;
    int wn = (wid & 1) * 64;
    const float* hcur = g_h[cur];
    const float* Bw = g_Bw + ((size_t)l * 11 + rr) * 16384;

    if (tid < 128) rows[tid] = g_joblist[jobs0 + tid];
    __syncthreads();

    float c[2][8][4];
    #pragma unroll
    for (int mi = 0; mi < 2; mi++)
        #pragma unroll
        for (int nj = 0; nj < 8; nj++)
            #pragma unroll
            for (int q = 0; q < 4; q++) c[mi][nj][q] = 0.f;

    const uint32_t* AsU = (const uint32_t*)As;
    const uint32_t* BsU = (const uint32_t*)Bs;

    #pragma unroll
    for (int i = 0; i < 4; i++) {
        int k0 = i * 32;
        float4 av[4], bv[4];
        #pragma unroll
        for (int t = 0; t < 4; t++) {
            int idx = tid + t * 256;            // 0..1023
            int r = idx >> 3, cc = idx & 7;
            av[t] = *(const float4*)&hcur[(size_t)rows[r] * HIDDEN + k0 + cc * 4];
        }
        #pragma unroll
        for (int t = 0; t < 4; t++) {
            int idx = tid + t * 256;            // 32x32 float4s
            int kk = idx >> 5, n4 = idx & 31;
            bv[t] = *(const float4*)&Bw[(size_t)(k0 + kk) * 128 + n4 * 4];
        }
        __syncthreads();
        #pragma unroll
        for (int t = 0; t < 4; t++) {
            int idx = tid + t * 256;
            int r = idx >> 3, cc = idx & 7;
            float4 cv = make_float4(f2tf32(av[t].x), f2tf32(av[t].y),
                                    f2tf32(av[t].z), f2tf32(av[t].w));
            *(float4*)&As[r * APITCH + cc * 4] = cv;
        }
        #pragma unroll
        for (int t = 0; t < 4; t++) {
            int idx = tid + t * 256;
            int kk = idx >> 5, n4 = idx & 31;
            *(float4*)&Bs[kk * BPITCH + n4 * 4] = bv[t];
        }
        __syncthreads();

        #pragma unroll
        for (int s = 0; s < 4; s++) {
            int kb = s * 8;
            uint32_t a[2][4], b[8][2];
            #pragma unroll
            for (int mi = 0; mi < 2; mi++) {
                int r = wm + mi * 16 + gq;
                a[mi][0] = AsU[r * APITCH + kb + tq];
                a[mi][1] = AsU[(r + 8) * APITCH + kb + tq];
                a[mi][2] = AsU[r * APITCH + kb + tq + 4];
                a[mi][3] = AsU[(r + 8) * APITCH + kb + tq + 4];
            }
            #pragma unroll
            for (int nj = 0; nj < 8; nj++) {
                int n = wn + nj * 8 + gq;
                b[nj][0] = BsU[(kb + tq) * BPITCH + n];
                b[nj][1] = BsU[(kb + tq + 4) * BPITCH + n];
            }
            #pragma unroll
            for (int mi = 0; mi < 2; mi++)
                #pragma unroll
                for (int nj = 0; nj < 8; nj++)
                    mma_tf32(c[mi][nj], a[mi], b[nj]);
        }
        __syncthreads();
    }

    // store to compact Y (fp16x2), rows always in-bounds (padded allocation)
    #pragma unroll
    for (int mi = 0; mi < 2; mi++) {
        int j0 = jobs0 + wm + mi * 16 + gq;
        #pragma unroll
        for (int nj = 0; nj < 8; nj++) {
            int cb = wn + nj * 8 + 2 * tq;
            g_Yc[(size_t)j0 * 64 + (cb >> 1)]       = pack_h2(c[mi][nj][0], c[mi][nj][1]);
            g_Yc[(size_t)(j0 + 8) * 64 + (cb >> 1)] = pack_h2(c[mi][nj][2], c[mi][nj][3]);
        }
    }
}

// ---------------- fused CSR gather + bias + LN + ReLU + residual ----------------
__device__ __forceinline__ void fma_h2(float4& acc, uint2 v, float w) {
    float2 a = __half22float2(*(__half2*)&v.x);
    float2 b = __half22float2(*(__half2*)&v.y);
    acc.x = fmaf(a.x, w, acc.x);
    acc.y = fmaf(a.y, w, acc.y);
    acc.z = fmaf(b.x, w, acc.z);
    acc.w = fmaf(b.y, w, acc.w);
}

__global__ void gather_ln_kernel(const float* __restrict__ conv_b, const float* __restrict__ ln_g,
                                 const float* __restrict__ ln_b, int l, int cur) {
    int wid = threadIdx.x >> 5;
    int lane = threadIdx.x & 31;
    int row = blockIdx.x * 8 + wid;
    if (row >= N_NODES) return;
    int n0 = lane * 4;
    int lo2 = lane * 2;
    const float* hcur = g_h[cur];
    float* hnext = g_h[cur ^ 1];

    float4 acc;
    {
        uint2 rv = *(const uint2*)&g_Yc[(size_t)row * 64 + lo2];   // root job = identity
        float2 a = __half22float2(*(__half2*)&rv.x);
        float2 b = __half22float2(*(__half2*)&rv.y);
        float4 cb = *(const float4*)&conv_b[l * HIDDEN + n0];
        acc.x = a.x + cb.x; acc.y = a.y + cb.y; acc.z = b.x + cb.z; acc.w = b.y + cb.w;
    }

    int s = g_start[row];
    int e = s + g_cntd[row];
    int i = s;
    for (; i + 4 <= e; i += 4) {
        int o0 = g_coff[i],     o1 = g_coff[i + 1];
        int o2 = g_coff[i + 2], o3 = g_coff[i + 3];
        float w0 = g_cw[i],     w1 = g_cw[i + 1];
        float w2 = g_cw[i + 2], w3 = g_cw[i + 3];
        uint2 v0 = *(const uint2*)&g_Yc[(size_t)o0 + lo2];
        uint2 v1 = *(const uint2*)&g_Yc[(size_t)o1 + lo2];
        uint2 v2 = *(const uint2*)&g_Yc[(size_t)o2 + lo2];
        uint2 v3 = *(const uint2*)&g_Yc[(size_t)o3 + lo2];
        fma_h2(acc, v0, w0);
        fma_h2(acc, v1, w1);
        fma_h2(acc, v2, w2);
        fma_h2(acc, v3, w3);
    }
    for (; i < e; i++) {
        uint2 v = *(const uint2*)&g_Yc[(size_t)g_coff[i] + lo2];
        fma_h2(acc, v, g_cw[i]);
    }

    float sm = acc.x + acc.y + acc.z + acc.w;
    float q = acc.x * acc.x + acc.y * acc.y + acc.z * acc.z + acc.w * acc.w;
    #pragma unroll
    for (int o = 16; o > 0; o >>= 1) {
        sm += __shfl_xor_sync(0xFFFFFFFFu, sm, o);
        q  += __shfl_xor_sync(0xFFFFFFFFu, q, o);
    }
    float mu = sm * (1.0f / HIDDEN);
    float var = q * (1.0f / HIDDEN) - mu * mu;
    float rs = rsqrtf(var + LN_EPS);
    float4 g4 = *(const float4*)&ln_g[l * HIDDEN + n0];
    float4 b4 = *(const float4*)&ln_b[l * HIDDEN + n0];
    float4 rv = *(const float4*)&hcur[(size_t)row * HIDDEN + n0];
    float4 o;
    o.x = fmaxf((acc.x - mu) * rs * g4.x + b4.x, 0.f) + rv.x;
    o.y = fmaxf((acc.y - mu) * rs * g4.y + b4.y, 0.f) + rv.y;
    o.z = fmaxf((acc.z - mu) * rs * g4.z + b4.z, 0.f) + rv.z;
    o.w = fmaxf((acc.w - mu) * rs * g4.w + b4.w, 0.f) + rv.w;
    *(float4*)&hnext[(size_t)row * HIDDEN + n0] = o;
}

// ---------------- pooling ----------------
__device__ __forceinline__ int lower_bound_dev(const int* __restrict__ a, int n, int v) {
    int lo = 0, hi = n;
    while (lo < hi) { int mid = (lo + hi) >> 1; if (a[mid] < v) lo = mid + 1; else hi = mid; }
    return lo;
}

__global__ void pool_kernel(const int* __restrict__ batch, float* __restrict__ out, int finalbuf) {
    int g = blockIdx.x;
    int tid = threadIdx.x;
    int start = lower_bound_dev(batch, N_NODES, g);
    int end   = lower_bound_dev(batch, N_NODES, g + 1);
    const float* h = g_h[finalbuf];
    float acc = 0.f;
    for (int i = start; i < end; i++)
        acc += h[(size_t)i * HIDDEN + tid];
    out[g * HIDDEN + tid] = acc;
}

// ---------------- launch ----------------
extern "C" void kernel_launch(void* const* d_in, const int* in_sizes, int n_in,
                              void* d_out, int out_size) {
    const float* x      = (const float*)d_in[0];
    const int* ei       = (const int*)d_in[1];
    const int* et       = (const int*)d_in[2];
    const int* batch    = (const int*)d_in[3];
    const float* Wp     = (const float*)d_in[4];
    const float* bp     = (const float*)d_in[5];
    const float* rel_w  = (const float*)d_in[6];
    const float* root_w = (const float*)d_in[7];
    const float* conv_b = (const float*)d_in[8];
    const float* ln_g   = (const float*)d_in[9];
    const float* ln_b   = (const float*)d_in[10];
    float* out = (float*)d_out;

    // structure setup
    init_kernel<<<(NRN + 255) / 256, 256>>>();
    count_kernel<<<(N_EDGES + 255) / 256, 256>>>(ei, et);
    scan_dst_kernel<<<1, 1024>>>();
    scanSR_kernel<<<1, 1024>>>();
    jobinit_kernel<<<(NJMAX + 255) / 256, 256>>>();
    jobbuild_kernel<<<(NRN + 255) / 256, 256>>>();
    fill_kernel<<<(N_EDGES + 255) / 256, 256>>>(ei, et);

    // weights packed once for all layers
    bw_kernel<<<(int)(((size_t)N_LAYERS * 11 * 16384 + 255) / 256), 256>>>(rel_w, root_w);

    proj_kernel<<<(N_NODES + BM - 1) / BM, 256>>>(x, Wp, bp);

    for (int l = 0; l < N_LAYERS; l++) {
        int cur = l & 1;
        gemmc_kernel<<<MAXTILES, 256>>>(cur, l);
        gather_ln_kernel<<<(N_NODES + 7) / 8, 256>>>(conv_b, ln_g, ln_b, l, cur);
    }

    pool_kernel<<<N_GRAPHS, HIDDEN>>>(batch, out, 0);
}

// round 13
// speedup vs baseline: 1.7802x; 1.3329x over previous
#include <cuda_runtime.h>
#include <cuda_fp16.h>
#include <cstdint>

#define N_NODES 50000
#define N_EDGES 600000
#define IN_DIM  64
#define HIDDEN  128
#define N_REL   10
#define N_LAYERS 6
#define N_GRAPHS 64
#define LN_EPS  1e-5f

#define NRN     (N_REL * N_NODES)          // 500000 (rel,src) slots
#define ROOTPAD 50048                      // pad128(50000)
#define NJMAX   (ROOTPAD * 11)             // worst-case padded job rows = 550528
#define MAXTILES (NJMAX / 128)             // 4301

#define SCAN_BLK  256
#define SCAN_GRID ((NRN + SCAN_BLK - 1) / SCAN_BLK)   // 1954

// ---------------- device scratch ----------------
__device__ uint32_t g_Yc[(size_t)NJMAX * 64];      // compact Y, fp16x2 per u32 (<=141MB)
__device__ float g_h[2][(size_t)N_NODES * HIDDEN]; // ping-pong features (fp32)
__device__ float g_Bw[(size_t)N_LAYERS * 11 * 128 * 128]; // packed tf32 weights [l][rr][k][n]
__device__ int   g_cnt[N_NODES * N_REL];           // in-degree per (dst,rel) -> mean weight
__device__ int   g_cntSR[NRN];                     // out-degree per (rel,src) -> compaction
__device__ int   g_cntd[N_NODES];                  // per-dst in-degree
__device__ int   g_start[N_NODES];                 // CSR offsets (by dst)
__device__ int   g_fill[N_NODES];                  // CSR fill cursors
__device__ int   g_jobrank[NRN];                   // global rank among flagged slots
__device__ int   g_cumRel[N_REL + 1];              // flagged count before each rel
__device__ int   g_jb[12];                         // job base per region (0=root), [11]=total
__device__ int   g_joblist[NJMAX];                 // job row -> src node
__device__ int   g_jobidx[NRN];                    // (rel,src) -> u32 offset into g_Yc
__device__ int   g_coff[N_EDGES];                  // per-edge u32 offset into g_Yc
__device__ float g_cw[N_EDGES];                    // per-edge weight 1/cnt(dst,rel)
__device__ int   g_blkcnt[SCAN_GRID];              // decoupled scan: per-block flag counts
__device__ int   g_blkbase[SCAN_GRID];             // decoupled scan: per-block bases

__device__ __forceinline__ float f2tf32(float f) {
    uint32_t r;
    asm("cvt.rna.tf32.f32 %0, %1;" : "=r"(r) : "f"(f));
    return __uint_as_float(r);
}

__device__ __forceinline__ uint32_t pack_h2(float lo, float hi) {
    __half2 h = __floats2half2_rn(lo, hi);
    return *(uint32_t*)&h;
}

__device__ __forceinline__ void mma_tf32(float* c, const uint32_t* a, const uint32_t* b) {
    asm volatile(
        "mma.sync.aligned.m16n8k8.row.col.f32.tf32.tf32.f32 "
        "{%0,%1,%2,%3}, {%4,%5,%6,%7}, {%8,%9}, {%0,%1,%2,%3};"
        : "+f"(c[0]), "+f"(c[1]), "+f"(c[2]), "+f"(c[3])
        : "r"(a[0]), "r"(a[1]), "r"(a[2]), "r"(a[3]), "r"(b[0]), "r"(b[1]));
}

// ---------------- setup kernels (once per call) ----------------
__global__ void init_kernel() {
    int i = blockIdx.x * blockDim.x + threadIdx.x;
    if (i < NRN) { g_cntSR[i] = 0; }
    if (i < N_NODES * N_REL) g_cnt[i] = 0;
    if (i < N_NODES) { g_cntd[i] = 0; g_fill[i] = 0; }
}

__global__ void count_kernel(const int* __restrict__ ei, const int* __restrict__ et) {
    int e = blockIdx.x * blockDim.x + threadIdx.x;
    if (e >= N_EDGES) return;
    int src = ei[e];
    int dst = ei[N_EDGES + e];
    int r = et[e];
    atomicAdd(&g_cnt[dst * N_REL + r], 1);
    atomicAdd(&g_cntSR[r * N_NODES + src], 1);
    atomicAdd(&g_cntd[dst], 1);
}

// single-block exclusive scan of g_cntd -> g_start (50K elems, cheap)
__global__ void scan_dst_kernel() {
    __shared__ int part[1024];
    int t = threadIdx.x;
    const int CH = (N_NODES + 1023) / 1024;
    int base = t * CH;
    int s = 0;
    for (int i = 0; i < CH; i++) {
        int idx = base + i;
        if (idx < N_NODES) s += g_cntd[idx];
    }
    part[t] = s;
    __syncthreads();
    for (int off = 1; off < 1024; off <<= 1) {
        int v = (t >= off) ? part[t - off] : 0;
        __syncthreads();
        part[t] += v;
        __syncthreads();
    }
    int run = (t > 0) ? part[t - 1] : 0;
    for (int i = 0; i < CH; i++) {
        int idx = base + i;
        if (idx < N_NODES) { g_start[idx] = run; run += g_cntd[idx]; }
    }
}

// ---- decoupled 3-phase scan over (rel,src) flags ----
// Phase A: per-block flag counts (1 element/thread, ballot+popc)
__global__ void scanSR_a_kernel() {
    int idx = blockIdx.x * SCAN_BLK + threadIdx.x;
    int lane = threadIdx.x & 31;
    int wid = threadIdx.x >> 5;
    int flag = (idx < NRN && g_cntSR[idx] > 0) ? 1 : 0;
    unsigned m = __ballot_sync(0xFFFFFFFFu, flag);
    __shared__ int wsum[SCAN_BLK / 32];
    if (lane == 0) wsum[wid] = __popc(m);
    __syncthreads();
    if (threadIdx.x == 0) {
        int s = 0;
        #pragma unroll
        for (int w = 0; w < SCAN_BLK / 32; w++) s += wsum[w];
        g_blkcnt[blockIdx.x] = s;
    }
}

// Phase B: single-block scan of the 1954 block counts -> g_blkbase, total
__global__ void scanSR_b_kernel() {
    __shared__ int part[1024];
    int t = threadIdx.x;
    const int CH = (SCAN_GRID + 1023) / 1024;   // 2
    int base = t * CH;
    int s = 0;
    #pragma unroll
    for (int i = 0; i < CH; i++) {
        int idx = base + i;
        if (idx < SCAN_GRID) s += g_blkcnt[idx];
    }
    part[t] = s;
    __syncthreads();
    for (int off = 1; off < 1024; off <<= 1) {
        int v = (t >= off) ? part[t - off] : 0;
        __syncthreads();
        part[t] += v;
        __syncthreads();
    }
    int run = (t > 0) ? part[t - 1] : 0;
    #pragma unroll
    for (int i = 0; i < CH; i++) {
        int idx = base + i;
        if (idx < SCAN_GRID) { g_blkbase[idx] = run; run += g_blkcnt[idx]; }
    }
    if (t == 1023) g_cumRel[N_REL] = part[1023];
}

// Phase C: per-element exclusive rank; scatter cumRel at rel boundaries
__global__ void scanSR_c_kernel() {
    int idx = blockIdx.x * SCAN_BLK + threadIdx.x;
    int lane = threadIdx.x & 31;
    int wid = threadIdx.x >> 5;
    int flag = (idx < NRN && g_cntSR[idx] > 0) ? 1 : 0;
    unsigned m = __ballot_sync(0xFFFFFFFFu, flag);
    int wpre = __popc(m & ((1u << lane) - 1));
    __shared__ int wsum[SCAN_BLK / 32];
    if (lane == 0) wsum[wid] = __popc(m);
    __syncthreads();
    int wbase = 0;
    #pragma unroll
    for (int w = 0; w < SCAN_BLK / 32; w++)
        if (w < wid) wbase += wsum[w];
    int rank = g_blkbase[blockIdx.x] + wbase + wpre;   // exclusive global rank at idx
    if (flag) g_jobrank[idx] = rank;
    if (idx < NRN && idx % N_NODES == 0) g_cumRel[idx / N_NODES] = rank;
}

// Phase D: job bases (trivial)
__global__ void jb_kernel() {
    g_jb[0] = 0;
    int b = ROOTPAD;
    for (int r = 0; r < N_REL; r++) {
        g_jb[1 + r] = b;
        int c = g_cumRel[r + 1] - g_cumRel[r];
        b += (c + 127) & ~127;
    }
    g_jb[11] = b;
}

__global__ void jobinit_kernel() {
    int i = blockIdx.x * blockDim.x + threadIdx.x;
    if (i < NJMAX) g_joblist[i] = (i < N_NODES) ? i : 0;
}

__global__ void jobbuild_kernel() {
    int i = blockIdx.x * blockDim.x + threadIdx.x;
    if (i >= NRN) return;
    if (g_cntSR[i] > 0) {
        int r = i / N_NODES, src = i % N_NODES;
        int idx = g_jb[1 + r] + (g_jobrank[i] - g_cumRel[r]);
        g_joblist[idx] = src;
        g_jobidx[i] = idx * 64;        // u32 offset, premultiplied
    }
}

__global__ void fill_kernel(const int* __restrict__ ei, const int* __restrict__ et) {
    int e = blockIdx.x * blockDim.x + threadIdx.x;
    if (e >= N_EDGES) return;
    int src = ei[e];
    int dst = ei[N_EDGES + e];
    int r   = et[e];
    int pos = g_start[dst] + atomicAdd(&g_fill[dst], 1);
    g_coff[pos] = g_jobidx[r * N_NODES + src];
    g_cw[pos]   = 1.0f / (float)g_cnt[dst * N_REL + r];
}

// pack weights: g_Bw[l][rr][k][n], rr=0 root, rr=1+r rel r (tf32-rounded)
__global__ void bw_kernel(const float* __restrict__ rel_w, const float* __restrict__ root_w) {
    size_t idx = (size_t)blockIdx.x * blockDim.x + threadIdx.x;
    if (idx >= (size_t)N_LAYERS * 11 * 16384) return;
    int l = idx / (11 * 16384);
    int rem = idx % (11 * 16384);
    int rr = rem / 16384;
    int k = (rem % 16384) / 128, n = rem % 128;
    float v;
    if (rr == 0)
        v = root_w[(size_t)l * 16384 + k * 128 + n];
    else
        v = rel_w[(size_t)l * N_REL * 16384 + (size_t)(rr - 1) * 16384 + k * 128 + n];
    g_Bw[idx] = f2tf32(v);
}

// ---------------- input projection ----------------
#define BM 64
#define BK 16
__global__ void proj_kernel(const float* __restrict__ x, const float* __restrict__ Wp,
                            const float* __restrict__ bp) {
    __shared__ float As[BK][BM + 4];
    __shared__ float Bs[BK][HIDDEN];
    int tid = threadIdx.x;
    int tm = tid >> 5, tn = tid & 31;
    int row0 = blockIdx.x * BM;
    float acc[8][4];
    #pragma unroll
    for (int i = 0; i < 8; i++)
        #pragma unroll
        for (int j = 0; j < 4; j++) acc[i][j] = 0.f;

    for (int k0 = 0; k0 < IN_DIM; k0 += BK) {
        {
            int r = tid >> 2, kc = (tid & 3) * 4, grow = row0 + r;
            float4 v = make_float4(0.f, 0.f, 0.f, 0.f);
            if (grow < N_NODES) v = *(const float4*)&x[(size_t)grow * IN_DIM + k0 + kc];
            As[kc + 0][r] = v.x; As[kc + 1][r] = v.y; As[kc + 2][r] = v.z; As[kc + 3][r] = v.w;
        }
        #pragma unroll
        for (int i = 0; i < 2; i++) {
            int f = tid + i * 256;
            int kk = f >> 5, c4 = (f & 31) * 4;
            *(float4*)&Bs[kk][c4] = *(const float4*)&Wp[(size_t)(k0 + kk) * HIDDEN + c4];
        }
        __syncthreads();
        #pragma unroll
        for (int kk = 0; kk < BK; kk++) {
            float a[8], b[4];
            *(float4*)&a[0] = *(const float4*)&As[kk][tm * 8];
            *(float4*)&a[4] = *(const float4*)&As[kk][tm * 8 + 4];
            *(float4*)&b[0] = *(const float4*)&Bs[kk][tn * 4];
            #pragma unroll
            for (int i = 0; i < 8; i++)
                #pragma unroll
                for (int j = 0; j < 4; j++) acc[i][j] = fmaf(a[i], b[j], acc[i][j]);
        }
        __syncthreads();
    }
    int n0 = tn * 4;
    float4 bb = *(const float4*)&bp[n0];
    #pragma unroll
    for (int i = 0; i < 8; i++) {
        int grow = row0 + tm * 8 + i;
        if (grow < N_NODES) {
            float4 o = make_float4(acc[i][0] + bb.x, acc[i][1] + bb.y,
                                   acc[i][2] + bb.z, acc[i][3] + bb.w);
            *(float4*)&g_h[0][(size_t)grow * HIDDEN + n0] = o;
        }
    }
}

// ---------------- compacted tf32 GEMM: g_Yc[job] = fp16(h[joblist[job]] @ W[rel(job)]) ----------------
#define APITCH 36
#define BPITCH 136

__global__ void __launch_bounds__(256, 2)
gemmc_kernel(int cur, int l) {
    __shared__ float As[128 * APITCH];
    __shared__ float Bs[32 * BPITCH];
    __shared__ int rows[128];

    int jobs0 = blockIdx.x * 128;
    if (jobs0 >= g_jb[11]) return;
    int rr = 0;
    #pragma unroll
    for (int r = 1; r < 11; r++)
        if (jobs0 >= g_jb[r]) rr = r;

    int tid = threadIdx.x;
    int wid = tid >> 5;
    int lane = tid & 31;
    int gq = lane >> 2;
    int tq = lane & 3;
    int wm = (wid >> 1) * 32;
    int wn = (wid & 1) * 64;
    const float* hcur = g_h[cur];
    const float* Bw = g_Bw + ((size_t)l * 11 + rr) * 16384;

    if (tid < 128) rows[tid] = g_joblist[jobs0 + tid];
    __syncthreads();

    float c[2][8][4];
    #pragma unroll
    for (int mi = 0; mi < 2; mi++)
        #pragma unroll
        for (int nj = 0; nj < 8; nj++)
            #pragma unroll
            for (int q = 0; q < 4; q++) c[mi][nj][q] = 0.f;

    const uint32_t* AsU = (const uint32_t*)As;
    const uint32_t* BsU = (const uint32_t*)Bs;

    #pragma unroll
    for (int i = 0; i < 4; i++) {
        int k0 = i * 32;
        float4 av[4], bv[4];
        #pragma unroll
        for (int t = 0; t < 4; t++) {
            int idx = tid + t * 256;            // 0..1023
            int r = idx >> 3, cc = idx & 7;
            av[t] = *(const float4*)&hcur[(size_t)rows[r] * HIDDEN + k0 + cc * 4];
        }
        #pragma unroll
        for (int t = 0; t < 4; t++) {
            int idx = tid + t * 256;            // 32x32 float4s
            int kk = idx >> 5, n4 = idx & 31;
            bv[t] = *(const float4*)&Bw[(size_t)(k0 + kk) * 128 + n4 * 4];
        }
        __syncthreads();
        #pragma unroll
        for (int t = 0; t < 4; t++) {
            int idx = tid + t * 256;
            int r = idx >> 3, cc = idx & 7;
            float4 cv = make_float4(f2tf32(av[t].x), f2tf32(av[t].y),
                                    f2tf32(av[t].z), f2tf32(av[t].w));
            *(float4*)&As[r * APITCH + cc * 4] = cv;
        }
        #pragma unroll
        for (int t = 0; t < 4; t++) {
            int idx = tid + t * 256;
            int kk = idx >> 5, n4 = idx & 31;
            *(float4*)&Bs[kk * BPITCH + n4 * 4] = bv[t];
        }
        __syncthreads();

        #pragma unroll
        for (int s = 0; s < 4; s++) {
            int kb = s * 8;
            uint32_t a[2][4], b[8][2];
            #pragma unroll
            for (int mi = 0; mi < 2; mi++) {
                int r = wm + mi * 16 + gq;
                a[mi][0] = AsU[r * APITCH + kb + tq];
                a[mi][1] = AsU[(r + 8) * APITCH + kb + tq];
                a[mi][2] = AsU[r * APITCH + kb + tq + 4];
                a[mi][3] = AsU[(r + 8) * APITCH + kb + tq + 4];
            }
            #pragma unroll
            for (int nj = 0; nj < 8; nj++) {
                int n = wn + nj * 8 + gq;
                b[nj][0] = BsU[(kb + tq) * BPITCH + n];
                b[nj][1] = BsU[(kb + tq + 4) * BPITCH + n];
            }
            #pragma unroll
            for (int mi = 0; mi < 2; mi++)
                #pragma unroll
                for (int nj = 0; nj < 8; nj++)
                    mma_tf32(c[mi][nj], a[mi], b[nj]);
        }
        __syncthreads();
    }

    // store to compact Y (fp16x2), rows always in-bounds (padded allocation)
    #pragma unroll
    for (int mi = 0; mi < 2; mi++) {
        int j0 = jobs0 + wm + mi * 16 + gq;
        #pragma unroll
        for (int nj = 0; nj < 8; nj++) {
            int cb = wn + nj * 8 + 2 * tq;
            g_Yc[(size_t)j0 * 64 + (cb >> 1)]       = pack_h2(c[mi][nj][0], c[mi][nj][1]);
            g_Yc[(size_t)(j0 + 8) * 64 + (cb >> 1)] = pack_h2(c[mi][nj][2], c[mi][nj][3]);
        }
    }
}

// ---------------- fused CSR gather + bias + LN + ReLU + residual ----------------
__device__ __forceinline__ void fma_h2(float4& acc, uint2 v, float w) {
    float2 a = __half22float2(*(__half2*)&v.x);
    float2 b = __half22float2(*(__half2*)&v.y);
    acc.x = fmaf(a.x, w, acc.x);
    acc.y = fmaf(a.y, w, acc.y);
    acc.z = fmaf(b.x, w, acc.z);
    acc.w = fmaf(b.y, w, acc.w);
}

__global__ void gather_ln_kernel(const float* __restrict__ conv_b, const float* __restrict__ ln_g,
                                 const float* __restrict__ ln_b, int l, int cur) {
    int wid = threadIdx.x >> 5;
    int lane = threadIdx.x & 31;
    int row = blockIdx.x * 8 + wid;
    if (row >= N_NODES) return;
    int n0 = lane * 4;
    int lo2 = lane * 2;
    const float* hcur = g_h[cur];
    float* hnext = g_h[cur ^ 1];

    float4 acc;
    {
        uint2 rv = *(const uint2*)&g_Yc[(size_t)row * 64 + lo2];   // root job = identity
        float2 a = __half22float2(*(__half2*)&rv.x);
        float2 b = __half22float2(*(__half2*)&rv.y);
        float4 cb = *(const float4*)&conv_b[l * HIDDEN + n0];
        acc.x = a.x + cb.x; acc.y = a.y + cb.y; acc.z = b.x + cb.z; acc.w = b.y + cb.w;
    }

    int s = g_start[row];
    int e = s + g_cntd[row];
    int i = s;
    for (; i + 4 <= e; i += 4) {
        int o0 = g_coff[i],     o1 = g_coff[i + 1];
        int o2 = g_coff[i + 2], o3 = g_coff[i + 3];
        float w0 = g_cw[i],     w1 = g_cw[i + 1];
        float w2 = g_cw[i + 2], w3 = g_cw[i + 3];
        uint2 v0 = *(const uint2*)&g_Yc[(size_t)o0 + lo2];
        uint2 v1 = *(const uint2*)&g_Yc[(size_t)o1 + lo2];
        uint2 v2 = *(const uint2*)&g_Yc[(size_t)o2 + lo2];
        uint2 v3 = *(const uint2*)&g_Yc[(size_t)o3 + lo2];
        fma_h2(acc, v0, w0);
        fma_h2(acc, v1, w1);
        fma_h2(acc, v2, w2);
        fma_h2(acc, v3, w3);
    }
    for (; i < e; i++) {
        uint2 v = *(const uint2*)&g_Yc[(size_t)g_coff[i] + lo2];
        fma_h2(acc, v, g_cw[i]);
    }

    float sm = acc.x + acc.y + acc.z + acc.w;
    float q = acc.x * acc.x + acc.y * acc.y + acc.z * acc.z + acc.w * acc.w;
    #pragma unroll
    for (int o = 16; o > 0; o >>= 1) {
        sm += __shfl_xor_sync(0xFFFFFFFFu, sm, o);
        q  += __shfl_xor_sync(0xFFFFFFFFu, q, o);
    }
    float mu = sm * (1.0f / HIDDEN);
    float var = q * (1.0f / HIDDEN) - mu * mu;
    float rs = rsqrtf(var + LN_EPS);
    float4 g4 = *(const float4*)&ln_g[l * HIDDEN + n0];
    float4 b4 = *(const float4*)&ln_b[l * HIDDEN + n0];
    float4 rv = *(const float4*)&hcur[(size_t)row * HIDDEN + n0];
    float4 o;
    o.x = fmaxf((acc.x - mu) * rs * g4.x + b4.x, 0.f) + rv.x;
    o.y = fmaxf((acc.y - mu) * rs * g4.y + b4.y, 0.f) + rv.y;
    o.z = fmaxf((acc.z - mu) * rs * g4.z + b4.z, 0.f) + rv.z;
    o.w = fmaxf((acc.w - mu) * rs * g4.w + b4.w, 0.f) + rv.w;
    *(float4*)&hnext[(size_t)row * HIDDEN + n0] = o;
}

// ---------------- pooling ----------------
__device__ __forceinline__ int lower_bound_dev(const int* __restrict__ a, int n, int v) {
    int lo = 0, hi = n;
    while (lo < hi) { int mid = (lo + hi) >> 1; if (a[mid] < v) lo = mid + 1; else hi = mid; }
    return lo;
}

__global__ void pool_kernel(const int* __restrict__ batch, float* __restrict__ out, int finalbuf) {
    int g = blockIdx.x;
    int tid = threadIdx.x;
    int start = lower_bound_dev(batch, N_NODES, g);
    int end   = lower_bound_dev(batch, N_NODES, g + 1);
    const float* h = g_h[finalbuf];
    float acc = 0.f;
    for (int i = start; i < end; i++)
        acc += h[(size_t)i * HIDDEN + tid];
    out[g * HIDDEN + tid] = acc;
}

// ---------------- launch ----------------
extern "C" void kernel_launch(void* const* d_in, const int* in_sizes, int n_in,
                              void* d_out, int out_size) {
    const float* x      = (const float*)d_in[0];
    const int* ei       = (const int*)d_in[1];
    const int* et       = (const int*)d_in[2];
    const int* batch    = (const int*)d_in[3];
    const float* Wp     = (const float*)d_in[4];
    const float* bp     = (const float*)d_in[5];
    const float* rel_w  = (const float*)d_in[6];
    const float* root_w = (const float*)d_in[7];
    const float* conv_b = (const float*)d_in[8];
    const float* ln_g   = (const float*)d_in[9];
    const float* ln_b   = (const float*)d_in[10];
    float* out = (float*)d_out;

    // structure setup
    init_kernel<<<(NRN + 255) / 256, 256>>>();
    count_kernel<<<(N_EDGES + 255) / 256, 256>>>(ei, et);
    scan_dst_kernel<<<1, 1024>>>();
    scanSR_a_kernel<<<SCAN_GRID, SCAN_BLK>>>();
    scanSR_b_kernel<<<1, 1024>>>();
    scanSR_c_kernel<<<SCAN_GRID, SCAN_BLK>>>();
    jb_kernel<<<1, 1>>>();
    jobinit_kernel<<<(NJMAX + 255) / 256, 256>>>();
    jobbuild_kernel<<<(NRN + 255) / 256, 256>>>();
    fill_kernel<<<(N_EDGES + 255) / 256, 256>>>(ei, et);

    // weights packed once for all layers
    bw_kernel<<<(int)(((size_t)N_LAYERS * 11 * 16384 + 255) / 256), 256>>>(rel_w, root_w);

    proj_kernel<<<(N_NODES + BM - 1) / BM, 256>>>(x, Wp, bp);

    for (int l = 0; l < N_LAYERS; l++) {
        int cur = l & 1;
        gemmc_kernel<<<MAXTILES, 256>>>(cur, l);
        gather_ln_kernel<<<(N_NODES + 7) / 8, 256>>>(conv_b, ln_g, ln_b, l, cur);
    }

    pool_kernel<<<N_GRAPHS, HIDDEN>>>(batch, out, 0);
}

// round 14
// speedup vs baseline: 2.0561x; 1.1550x over previous
#include <cuda_runtime.h>
#include <cuda_fp16.h>
#include <cstdint>

#define N_NODES 50000
#define N_EDGES 600000
#define IN_DIM  64
#define HIDDEN  128
#define N_REL   10
#define N_LAYERS 6
#define N_GRAPHS 64
#define LN_EPS  1e-5f

#define NRN     (N_REL * N_NODES)          // 500000 (rel,src) slots
#define ROOTPAD 50048                      // pad128(50000)
#define NJMAX   (ROOTPAD * 11)             // worst-case padded job rows = 550528
#define MAXTILES (NJMAX / 128)             // 4301

#define SCAN_BLK  256
#define SCAN_GRID ((NRN + SCAN_BLK - 1) / SCAN_BLK)   // 1954

// ---------------- device scratch ----------------
__device__ uint32_t g_Yc[(size_t)NJMAX * 64];      // compact Y, fp16x2 per u32 (<=141MB)
__device__ float g_h[2][(size_t)N_NODES * HIDDEN]; // ping-pong features (fp32)
__device__ __half g_Bwh[(size_t)N_LAYERS * 11 * 128 * 128]; // fp16 weights [l][rr][n][k] (transposed!)
__device__ int   g_cnt[N_NODES * N_REL];           // in-degree per (dst,rel) -> mean weight
__device__ int   g_cntSR[NRN];                     // out-degree per (rel,src) -> compaction
__device__ int   g_cntd[N_NODES];                  // per-dst in-degree
__device__ int   g_start[N_NODES];                 // CSR offsets (by dst)
__device__ int   g_fill[N_NODES];                  // CSR fill cursors
__device__ int   g_jobrank[NRN];                   // global rank among flagged slots
__device__ int   g_cumRel[N_REL + 1];              // flagged count before each rel
__device__ int   g_jb[12];                         // job base per region (0=root), [11]=total
__device__ int   g_joblist[NJMAX];                 // job row -> src node
__device__ int   g_jobidx[NRN];                    // (rel,src) -> u32 offset into g_Yc
__device__ int   g_coff[N_EDGES];                  // per-edge u32 offset into g_Yc
__device__ float g_cw[N_EDGES];                    // per-edge weight 1/cnt(dst,rel)
__device__ int   g_blkcnt[SCAN_GRID];              // decoupled scan: per-block flag counts
__device__ int   g_blkbase[SCAN_GRID];             // decoupled scan: per-block bases

__device__ __forceinline__ uint32_t pack_h2(float lo, float hi) {
    __half2 h = __floats2half2_rn(lo, hi);
    return *(uint32_t*)&h;
}

__device__ __forceinline__ void mma_f16(float* c, const uint32_t* a, const uint32_t* b) {
    asm volatile(
        "mma.sync.aligned.m16n8k16.row.col.f32.f16.f16.f32 "
        "{%0,%1,%2,%3}, {%4,%5,%6,%7}, {%8,%9}, {%0,%1,%2,%3};"
        : "+f"(c[0]), "+f"(c[1]), "+f"(c[2]), "+f"(c[3])
        : "r"(a[0]), "r"(a[1]), "r"(a[2]), "r"(a[3]), "r"(b[0]), "r"(b[1]));
}

// ---------------- setup kernels (once per call) ----------------
__global__ void init_kernel() {
    int i = blockIdx.x * blockDim.x + threadIdx.x;
    if (i < NRN) { g_cntSR[i] = 0; }
    if (i < N_NODES * N_REL) g_cnt[i] = 0;
    if (i < N_NODES) { g_cntd[i] = 0; g_fill[i] = 0; }
}

__global__ void count_kernel(const int* __restrict__ ei, const int* __restrict__ et) {
    int e = blockIdx.x * blockDim.x + threadIdx.x;
    if (e >= N_EDGES) return;
    int src = ei[e];
    int dst = ei[N_EDGES + e];
    int r = et[e];
    atomicAdd(&g_cnt[dst * N_REL + r], 1);
    atomicAdd(&g_cntSR[r * N_NODES + src], 1);
    atomicAdd(&g_cntd[dst], 1);
}

// single-block exclusive scan of g_cntd -> g_start (50K elems, cheap)
__global__ void scan_dst_kernel() {
    __shared__ int part[1024];
    int t = threadIdx.x;
    const int CH = (N_NODES + 1023) / 1024;
    int base = t * CH;
    int s = 0;
    for (int i = 0; i < CH; i++) {
        int idx = base + i;
        if (idx < N_NODES) s += g_cntd[idx];
    }
    part[t] = s;
    __syncthreads();
    for (int off = 1; off < 1024; off <<= 1) {
        int v = (t >= off) ? part[t - off] : 0;
        __syncthreads();
        part[t] += v;
        __syncthreads();
    }
    int run = (t > 0) ? part[t - 1] : 0;
    for (int i = 0; i < CH; i++) {
        int idx = base + i;
        if (idx < N_NODES) { g_start[idx] = run; run += g_cntd[idx]; }
    }
}

// ---- decoupled 3-phase scan over (rel,src) flags ----
__global__ void scanSR_a_kernel() {
    int idx = blockIdx.x * SCAN_BLK + threadIdx.x;
    int lane = threadIdx.x & 31;
    int wid = threadIdx.x >> 5;
    int flag = (idx < NRN && g_cntSR[idx] > 0) ? 1 : 0;
    unsigned m = __ballot_sync(0xFFFFFFFFu, flag);
    __shared__ int wsum[SCAN_BLK / 32];
    if (lane == 0) wsum[wid] = __popc(m);
    __syncthreads();
    if (threadIdx.x == 0) {
        int s = 0;
        #pragma unroll
        for (int w = 0; w < SCAN_BLK / 32; w++) s += wsum[w];
        g_blkcnt[blockIdx.x] = s;
    }
}

__global__ void scanSR_b_kernel() {
    __shared__ int part[1024];
    int t = threadIdx.x;
    const int CH = (SCAN_GRID + 1023) / 1024;   // 2
    int base = t * CH;
    int s = 0;
    #pragma unroll
    for (int i = 0; i < CH; i++) {
        int idx = base + i;
        if (idx < SCAN_GRID) s += g_blkcnt[idx];
    }
    part[t] = s;
    __syncthreads();
    for (int off = 1; off < 1024; off <<= 1) {
        int v = (t >= off) ? part[t - off] : 0;
        __syncthreads();
        part[t] += v;
        __syncthreads();
    }
    int run = (t > 0) ? part[t - 1] : 0;
    #pragma unroll
    for (int i = 0; i < CH; i++) {
        int idx = base + i;
        if (idx < SCAN_GRID) { g_blkbase[idx] = run; run += g_blkcnt[idx]; }
    }
    if (t == 1023) g_cumRel[N_REL] = part[1023];
}

__global__ void scanSR_c_kernel() {
    int idx = blockIdx.x * SCAN_BLK + threadIdx.x;
    int lane = threadIdx.x & 31;
    int wid = threadIdx.x >> 5;
    int flag = (idx < NRN && g_cntSR[idx] > 0) ? 1 : 0;
    unsigned m = __ballot_sync(0xFFFFFFFFu, flag);
    int wpre = __popc(m & ((1u << lane) - 1));
    __shared__ int wsum[SCAN_BLK / 32];
    if (lane == 0) wsum[wid] = __popc(m);
    __syncthreads();
    int wbase = 0;
    #pragma unroll
    for (int w = 0; w < SCAN_BLK / 32; w++)
        if (w < wid) wbase += wsum[w];
    int rank = g_blkbase[blockIdx.x] + wbase + wpre;
    if (flag) g_jobrank[idx] = rank;
    if (idx < NRN && idx % N_NODES == 0) g_cumRel[idx / N_NODES] = rank;
}

__global__ void jb_kernel() {
    g_jb[0] = 0;
    int b = ROOTPAD;
    for (int r = 0; r < N_REL; r++) {
        g_jb[1 + r] = b;
        int c = g_cumRel[r + 1] - g_cumRel[r];
        b += (c + 127) & ~127;
    }
    g_jb[11] = b;
}

__global__ void jobinit_kernel() {
    int i = blockIdx.x * blockDim.x + threadIdx.x;
    if (i < NJMAX) g_joblist[i] = (i < N_NODES) ? i : 0;
}

__global__ void jobbuild_kernel() {
    int i = blockIdx.x * blockDim.x + threadIdx.x;
    if (i >= NRN) return;
    if (g_cntSR[i] > 0) {
        int r = i / N_NODES, src = i % N_NODES;
        int idx = g_jb[1 + r] + (g_jobrank[i] - g_cumRel[r]);
        g_joblist[idx] = src;
        g_jobidx[i] = idx * 64;        // u32 offset, premultiplied
    }
}

__global__ void fill_kernel(const int* __restrict__ ei, const int* __restrict__ et) {
    int e = blockIdx.x * blockDim.x + threadIdx.x;
    if (e >= N_EDGES) return;
    int src = ei[e];
    int dst = ei[N_EDGES + e];
    int r   = et[e];
    int pos = g_start[dst] + atomicAdd(&g_fill[dst], 1);
    g_coff[pos] = g_jobidx[r * N_NODES + src];
    g_cw[pos]   = 1.0f / (float)g_cnt[dst * N_REL + r];
}

// pack weights TRANSPOSED as fp16: g_Bwh[l][rr][n][k] = W[k][n]
__global__ void bw_kernel(const float* __restrict__ rel_w, const float* __restrict__ root_w) {
    size_t idx = (size_t)blockIdx.x * blockDim.x + threadIdx.x;
    if (idx >= (size_t)N_LAYERS * 11 * 16384) return;
    int l = idx / (11 * 16384);
    int rem = idx % (11 * 16384);
    int rr = rem / 16384;
    int n = (rem % 16384) / 128, k = rem % 128;
    float v;
    if (rr == 0)
        v = root_w[(size_t)l * 16384 + k * 128 + n];
    else
        v = rel_w[(size_t)l * N_REL * 16384 + (size_t)(rr - 1) * 16384 + k * 128 + n];
    g_Bwh[idx] = __float2half_rn(v);
}

// ---------------- input projection ----------------
#define BM 64
#define BK 16
__global__ void proj_kernel(const float* __restrict__ x, const float* __restrict__ Wp,
                            const float* __restrict__ bp) {
    __shared__ float As[BK][BM + 4];
    __shared__ float Bs[BK][HIDDEN];
    int tid = threadIdx.x;
    int tm = tid >> 5, tn = tid & 31;
    int row0 = blockIdx.x * BM;
    float acc[8][4];
    #pragma unroll
    for (int i = 0; i < 8; i++)
        #pragma unroll
        for (int j = 0; j < 4; j++) acc[i][j] = 0.f;

    for (int k0 = 0; k0 < IN_DIM; k0 += BK) {
        {
            int r = tid >> 2, kc = (tid & 3) * 4, grow = row0 + r;
            float4 v = make_float4(0.f, 0.f, 0.f, 0.f);
            if (grow < N_NODES) v = *(const float4*)&x[(size_t)grow * IN_DIM + k0 + kc];
            As[kc + 0][r] = v.x; As[kc + 1][r] = v.y; As[kc + 2][r] = v.z; As[kc + 3][r] = v.w;
        }
        #pragma unroll
        for (int i = 0; i < 2; i++) {
            int f = tid + i * 256;
            int kk = f >> 5, c4 = (f & 31) * 4;
            *(float4*)&Bs[kk][c4] = *(const float4*)&Wp[(size_t)(k0 + kk) * HIDDEN + c4];
        }
        __syncthreads();
        #pragma unroll
        for (int kk = 0; kk < BK; kk++) {
            float a[8], b[4];
            *(float4*)&a[0] = *(const float4*)&As[kk][tm * 8];
            *(float4*)&a[4] = *(const float4*)&As[kk][tm * 8 + 4];
            *(float4*)&b[0] = *(const float4*)&Bs[kk][tn * 4];
            #pragma unroll
            for (int i = 0; i < 8; i++)
                #pragma unroll
                for (int j = 0; j < 4; j++) acc[i][j] = fmaf(a[i], b[j], acc[i][j]);
        }
        __syncthreads();
    }
    int n0 = tn * 4;
    float4 bb = *(const float4*)&bp[n0];
    #pragma unroll
    for (int i = 0; i < 8; i++) {
        int grow = row0 + tm * 8 + i;
        if (grow < N_NODES) {
            float4 o = make_float4(acc[i][0] + bb.x, acc[i][1] + bb.y,
                                   acc[i][2] + bb.z, acc[i][3] + bb.w);
            *(float4*)&g_h[0][(size_t)grow * HIDDEN + n0] = o;
        }
    }
}

// ---------------- compacted fp16 GEMM: g_Yc[job] = fp16(h[joblist[job]] @ W[rel(job)]) ----------------
// CTA 128(M)x128(N), K chunked 2x64. Warp tile 32x64. m16n8k16 fp16, fp32 accum.
// SMEM pitch 72 halves = 36 words; 36 mod 32 = 4 -> conflict-free fragment loads.
#define APH 72
#define BPH 72

__global__ void __launch_bounds__(256, 2)
gemmc_kernel(int cur, int l) {
    __shared__ __half As[128 * APH];     // [m][k-chunk]
    __shared__ __half Bs[128 * BPH];     // [n][k-chunk]
    __shared__ int rows[128];

    int jobs0 = blockIdx.x * 128;
    if (jobs0 >= g_jb[11]) return;
    int rr = 0;
    #pragma unroll
    for (int r = 1; r < 11; r++)
        if (jobs0 >= g_jb[r]) rr = r;

    int tid = threadIdx.x;
    int wid = tid >> 5;
    int lane = tid & 31;
    int gq = lane >> 2;
    int tq = lane & 3;
    int wm = (wid >> 1) * 32;
    int wn = (wid & 1) * 64;
    const float* hcur = g_h[cur];
    const __half* Bw = g_Bwh + ((size_t)l * 11 + rr) * 16384;

    if (tid < 128) rows[tid] = g_joblist[jobs0 + tid];
    __syncthreads();

    float c[2][8][4];
    #pragma unroll
    for (int mi = 0; mi < 2; mi++)
        #pragma unroll
        for (int nj = 0; nj < 8; nj++)
            #pragma unroll
            for (int q = 0; q < 4; q++) c[mi][nj][q] = 0.f;

    const uint32_t* AsU = (const uint32_t*)As;
    const uint32_t* BsU = (const uint32_t*)Bs;

    #pragma unroll
    for (int ch = 0; ch < 2; ch++) {
        int k0 = ch * 64;
        // A: 128 rows x 64 floats -> fp16 smem. 2048 float4 loads / 256 thr = 8 each.
        float4 av[8];
        #pragma unroll
        for (int t = 0; t < 8; t++) {
            int idx = tid + t * 256;          // 0..2047
            int r = idx >> 4, c4 = idx & 15;
            av[t] = *(const float4*)&hcur[(size_t)rows[r] * HIDDEN + k0 + c4 * 4];
        }
        // B: 128 n-rows x 64 halves. 1024 float4(8-half) loads / 256 thr = 4 each.
        float4 bv[4];
        #pragma unroll
        for (int t = 0; t < 4; t++) {
            int idx = tid + t * 256;          // 0..1023
            int n = idx >> 3, u = idx & 7;
            bv[t] = *(const float4*)&Bw[(size_t)n * 128 + k0 + u * 8];
        }
        __syncthreads();    // previous chunk's mma done
        #pragma unroll
        for (int t = 0; t < 8; t++) {
            int idx = tid + t * 256;
            int r = idx >> 4, c4 = idx & 15;
            uint2 hv;
            hv.x = pack_h2(av[t].x, av[t].y);
            hv.y = pack_h2(av[t].z, av[t].w);
            *(uint2*)&As[r * APH + c4 * 4] = hv;
        }
        #pragma unroll
        for (int t = 0; t < 4; t++) {
            int idx = tid + t * 256;
            int n = idx >> 3, u = idx & 7;
            *(float4*)&Bs[n * BPH + u * 8] = bv[t];
        }
        __syncthreads();

        // 4 k-steps of 16
        #pragma unroll
        for (int s = 0; s < 4; s++) {
            uint32_t a[2][4], b[8][2];
            #pragma unroll
            for (int mi = 0; mi < 2; mi++) {
                int r = wm + mi * 16 + gq;
                a[mi][0] = AsU[r * (APH / 2) + s * 8 + tq];
                a[mi][1] = AsU[(r + 8) * (APH / 2) + s * 8 + tq];
                a[mi][2] = AsU[r * (APH / 2) + s * 8 + tq + 4];
                a[mi][3] = AsU[(r + 8) * (APH / 2) + s * 8 + tq + 4];
            }
            #pragma unroll
            for (int nj = 0; nj < 8; nj++) {
                int n = wn + nj * 8 + gq;
                b[nj][0] = BsU[n * (BPH / 2) + s * 8 + tq];
                b[nj][1] = BsU[n * (BPH / 2) + s * 8 + tq + 4];
            }
            #pragma unroll
            for (int mi = 0; mi < 2; mi++)
                #pragma unroll
                for (int nj = 0; nj < 8; nj++)
                    mma_f16(c[mi][nj], a[mi], b[nj]);
        }
        __syncthreads();
    }

    // store to compact Y (fp16x2), rows always in-bounds (padded allocation)
    #pragma unroll
    for (int mi = 0; mi < 2; mi++) {
        int j0 = jobs0 + wm + mi * 16 + gq;
        #pragma unroll
        for (int nj = 0; nj < 8; nj++) {
            int cb = wn + nj * 8 + 2 * tq;
            g_Yc[(size_t)j0 * 64 + (cb >> 1)]       = pack_h2(c[mi][nj][0], c[mi][nj][1]);
            g_Yc[(size_t)(j0 + 8) * 64 + (cb >> 1)] = pack_h2(c[mi][nj][2], c[mi][nj][3]);
        }
    }
}

// ---------------- fused CSR gather + bias + LN + ReLU + residual ----------------
__device__ __forceinline__ void fma_h2(float4& acc, uint2 v, float w) {
    float2 a = __half22float2(*(__half2*)&v.x);
    float2 b = __half22float2(*(__half2*)&v.y);
    acc.x = fmaf(a.x, w, acc.x);
    acc.y = fmaf(a.y, w, acc.y);
    acc.z = fmaf(b.x, w, acc.z);
    acc.w = fmaf(b.y, w, acc.w);
}

__global__ void gather_ln_kernel(const float* __restrict__ conv_b, const float* __restrict__ ln_g,
                                 const float* __restrict__ ln_b, int l, int cur) {
    int wid = threadIdx.x >> 5;
    int lane = threadIdx.x & 31;
    int row = blockIdx.x * 8 + wid;
    if (row >= N_NODES) return;
    int n0 = lane * 4;
    int lo2 = lane * 2;
    const float* hcur = g_h[cur];
    float* hnext = g_h[cur ^ 1];

    float4 acc;
    {
        uint2 rv = *(const uint2*)&g_Yc[(size_t)row * 64 + lo2];   // root job = identity
        float2 a = __half22float2(*(__half2*)&rv.x);
        float2 b = __half22float2(*(__half2*)&rv.y);
        float4 cb = *(const float4*)&conv_b[l * HIDDEN + n0];
        acc.x = a.x + cb.x; acc.y = a.y + cb.y; acc.z = b.x + cb.z; acc.w = b.y + cb.w;
    }

    int s = g_start[row];
    int e = s + g_cntd[row];
    int i = s;
    for (; i + 4 <= e; i += 4) {
        int o0 = g_coff[i],     o1 = g_coff[i + 1];
        int o2 = g_coff[i + 2], o3 = g_coff[i + 3];
        float w0 = g_cw[i],     w1 = g_cw[i + 1];
        float w2 = g_cw[i + 2], w3 = g_cw[i + 3];
        uint2 v0 = *(const uint2*)&g_Yc[(size_t)o0 + lo2];
        uint2 v1 = *(const uint2*)&g_Yc[(size_t)o1 + lo2];
        uint2 v2 = *(const uint2*)&g_Yc[(size_t)o2 + lo2];
        uint2 v3 = *(const uint2*)&g_Yc[(size_t)o3 + lo2];
        fma_h2(acc, v0, w0);
        fma_h2(acc, v1, w1);
        fma_h2(acc, v2, w2);
        fma_h2(acc, v3, w3);
    }
    for (; i < e; i++) {
        uint2 v = *(const uint2*)&g_Yc[(size_t)g_coff[i] + lo2];
        fma_h2(acc, v, g_cw[i]);
    }

    float sm = acc.x + acc.y + acc.z + acc.w;
    float q = acc.x * acc.x + acc.y * acc.y + acc.z * acc.z + acc.w * acc.w;
    #pragma unroll
    for (int o = 16; o > 0; o >>= 1) {
        sm += __shfl_xor_sync(0xFFFFFFFFu, sm, o);
        q  += __shfl_xor_sync(0xFFFFFFFFu, q, o);
    }
    float mu = sm * (1.0f / HIDDEN);
    float var = q * (1.0f / HIDDEN) - mu * mu;
    float rs = rsqrtf(var + LN_EPS);
    float4 g4 = *(const float4*)&ln_g[l * HIDDEN + n0];
    float4 b4 = *(const float4*)&ln_b[l * HIDDEN + n0];
    float4 rv = *(const float4*)&hcur[(size_t)row * HIDDEN + n0];
    float4 o;
    o.x = fmaxf((acc.x - mu) * rs * g4.x + b4.x, 0.f) + rv.x;
    o.y = fmaxf((acc.y - mu) * rs * g4.y + b4.y, 0.f) + rv.y;
    o.z = fmaxf((acc.z - mu) * rs * g4.z + b4.z, 0.f) + rv.z;
    o.w = fmaxf((acc.w - mu) * rs * g4.w + b4.w, 0.f) + rv.w;
    *(float4*)&hnext[(size_t)row * HIDDEN + n0] = o;
}

// ---------------- pooling ----------------
__device__ __forceinline__ int lower_bound_dev(const int* __restrict__ a, int n, int v) {
    int lo = 0, hi = n;
    while (lo < hi) { int mid = (lo + hi) >> 1; if (a[mid] < v) lo = mid + 1; else hi = mid; }
    return lo;
}

__global__ void pool_kernel(const int* __restrict__ batch, float* __restrict__ out, int finalbuf) {
    int g = blockIdx.x;
    int tid = threadIdx.x;
    int start = lower_bound_dev(batch, N_NODES, g);
    int end   = lower_bound_dev(batch, N_NODES, g + 1);
    const float* h = g_h[finalbuf];
    float acc = 0.f;
    for (int i = start; i < end; i++)
        acc += h[(size_t)i * HIDDEN + tid];
    out[g * HIDDEN + tid] = acc;
}

// ---------------- launch ----------------
extern "C" void kernel_launch(void* const* d_in, const int* in_sizes, int n_in,
                              void* d_out, int out_size) {
    const float* x      = (const float*)d_in[0];
    const int* ei       = (const int*)d_in[1];
    const int* et       = (const int*)d_in[2];
    const int* batch    = (const int*)d_in[3];
    const float* Wp     = (const float*)d_in[4];
    const float* bp     = (const float*)d_in[5];
    const float* rel_w  = (const float*)d_in[6];
    const float* root_w = (const float*)d_in[7];
    const float* conv_b = (const float*)d_in[8];
    const float* ln_g   = (const float*)d_in[9];
    const float* ln_b   = (const float*)d_in[10];
    float* out = (float*)d_out;

    // structure setup
    init_kernel<<<(NRN + 255) / 256, 256>>>();
    count_kernel<<<(N_EDGES + 255) / 256, 256>>>(ei, et);
    scan_dst_kernel<<<1, 1024>>>();
    scanSR_a_kernel<<<SCAN_GRID, SCAN_BLK>>>();
    scanSR_b_kernel<<<1, 1024>>>();
    scanSR_c_kernel<<<SCAN_GRID, SCAN_BLK>>>();
    jb_kernel<<<1, 1>>>();
    jobinit_kernel<<<(NJMAX + 255) / 256, 256>>>();
    jobbuild_kernel<<<(NRN + 255) / 256, 256>>>();
    fill_kernel<<<(N_EDGES + 255) / 256, 256>>>(ei, et);

    // weights packed once for all layers (fp16, transposed)
    bw_kernel<<<(int)(((size_t)N_LAYERS * 11 * 16384 + 255) / 256), 256>>>(rel_w, root_w);

    proj_kernel<<<(N_NODES + BM - 1) / BM, 256>>>(x, Wp, bp);

    for (int l = 0; l < N_LAYERS; l++) {
        int cur = l & 1;
        gemmc_kernel<<<MAXTILES, 256>>>(cur, l);
        gather_ln_kernel<<<(N_NODES + 7) / 8, 256>>>(conv_b, ln_g, ln_b, l, cur);
    }

    pool_kernel<<<N_GRAPHS, HIDDEN>>>(batch, out, 0);
}

// round 15
// speedup vs baseline: 2.1101x; 1.0263x over previous
#include <cuda_runtime.h>
#include <cuda_fp16.h>
#include <cstdint>

#define N_NODES 50000
#define N_EDGES 600000
#define IN_DIM  64
#define HIDDEN  128
#define N_REL   10
#define N_LAYERS 6
#define N_GRAPHS 64
#define LN_EPS  1e-5f

#define NRN     (N_REL * N_NODES)          // 500000 (rel,src) slots
#define ROOTPAD 50048                      // pad128(50000)
#define NJMAX   (ROOTPAD * 11)             // worst-case padded job rows = 550528
#define MAXTILES (NJMAX / 128)             // 4301

#define SCAN_BLK  256
#define SCAN_GRID ((NRN + SCAN_BLK - 1) / SCAN_BLK)   // 1954

// ---------------- device scratch ----------------
__device__ uint32_t g_Yc[(size_t)NJMAX * 64];      // compact Y, fp16x2 per u32 (<=141MB)
__device__ float g_h[2][(size_t)N_NODES * HIDDEN]; // ping-pong features (fp32)
__device__ __half g_hh[(size_t)N_NODES * HIDDEN];  // fp16 copy of current h (GEMM A side)
__device__ __half g_Bwh[(size_t)N_LAYERS * 11 * 128 * 128]; // fp16 weights [l][rr][n][k] (transposed)
__device__ int   g_cnt[N_NODES * N_REL];           // in-degree per (dst,rel) -> mean weight
__device__ int   g_cntSR[NRN];                     // out-degree per (rel,src) -> compaction
__device__ int   g_cntd[N_NODES];                  // per-dst in-degree
__device__ int   g_start[N_NODES];                 // CSR offsets (by dst)
__device__ int   g_fill[N_NODES];                  // CSR fill cursors
__device__ int   g_jobrank[NRN];                   // global rank among flagged slots
__device__ int   g_cumRel[N_REL + 1];              // flagged count before each rel
__device__ int   g_jb[12];                         // job base per region (0=root), [11]=total
__device__ int   g_joblist[NJMAX];                 // job row -> src node
__device__ int   g_jobidx[NRN];                    // (rel,src) -> u32 offset into g_Yc
__device__ int2  g_epk[N_EDGES];                   // per-edge packed {coff, cw bits}
__device__ int   g_blkcnt[SCAN_GRID];
__device__ int   g_blkbase[SCAN_GRID];

__device__ __forceinline__ uint32_t pack_h2(float lo, float hi) {
    __half2 h = __floats2half2_rn(lo, hi);
    return *(uint32_t*)&h;
}

__device__ __forceinline__ void mma_f16(float* c, const uint32_t* a, const uint32_t* b) {
    asm volatile(
        "mma.sync.aligned.m16n8k16.row.col.f32.f16.f16.f32 "
        "{%0,%1,%2,%3}, {%4,%5,%6,%7}, {%8,%9}, {%0,%1,%2,%3};"
        : "+f"(c[0]), "+f"(c[1]), "+f"(c[2]), "+f"(c[3])
        : "r"(a[0]), "r"(a[1]), "r"(a[2]), "r"(a[3]), "r"(b[0]), "r"(b[1]));
}

// ---------------- setup kernels (once per call) ----------------
__global__ void init_kernel() {
    int i = blockIdx.x * blockDim.x + threadIdx.x;
    if (i < NRN) { g_cntSR[i] = 0; }
    if (i < N_NODES * N_REL) g_cnt[i] = 0;
    if (i < N_NODES) { g_cntd[i] = 0; g_fill[i] = 0; }
}

__global__ void count_kernel(const int* __restrict__ ei, const int* __restrict__ et) {
    int e = blockIdx.x * blockDim.x + threadIdx.x;
    if (e >= N_EDGES) return;
    int src = ei[e];
    int dst = ei[N_EDGES + e];
    int r = et[e];
    atomicAdd(&g_cnt[dst * N_REL + r], 1);
    atomicAdd(&g_cntSR[r * N_NODES + src], 1);
    atomicAdd(&g_cntd[dst], 1);
}

__global__ void scan_dst_kernel() {
    __shared__ int part[1024];
    int t = threadIdx.x;
    const int CH = (N_NODES + 1023) / 1024;
    int base = t * CH;
    int s = 0;
    for (int i = 0; i < CH; i++) {
        int idx = base + i;
        if (idx < N_NODES) s += g_cntd[idx];
    }
    part[t] = s;
    __syncthreads();
    for (int off = 1; off < 1024; off <<= 1) {
        int v = (t >= off) ? part[t - off] : 0;
        __syncthreads();
        part[t] += v;
        __syncthreads();
    }
    int run = (t > 0) ? part[t - 1] : 0;
    for (int i = 0; i < CH; i++) {
        int idx = base + i;
        if (idx < N_NODES) { g_start[idx] = run; run += g_cntd[idx]; }
    }
}

__global__ void scanSR_a_kernel() {
    int idx = blockIdx.x * SCAN_BLK + threadIdx.x;
    int lane = threadIdx.x & 31;
    int wid = threadIdx.x >> 5;
    int flag = (idx < NRN && g_cntSR[idx] > 0) ? 1 : 0;
    unsigned m = __ballot_sync(0xFFFFFFFFu, flag);
    __shared__ int wsum[SCAN_BLK / 32];
    if (lane == 0) wsum[wid] = __popc(m);
    __syncthreads();
    if (threadIdx.x == 0) {
        int s = 0;
        #pragma unroll
        for (int w = 0; w < SCAN_BLK / 32; w++) s += wsum[w];
        g_blkcnt[blockIdx.x] = s;
    }
}

__global__ void scanSR_b_kernel() {
    __shared__ int part[1024];
    int t = threadIdx.x;
    const int CH = (SCAN_GRID + 1023) / 1024;   // 2
    int base = t * CH;
    int s = 0;
    #pragma unroll
    for (int i = 0; i < CH; i++) {
        int idx = base + i;
        if (idx < SCAN_GRID) s += g_blkcnt[idx];
    }
    part[t] = s;
    __syncthreads();
    for (int off = 1; off < 1024; off <<= 1) {
        int v = (t >= off) ? part[t - off] : 0;
        __syncthreads();
        part[t] += v;
        __syncthreads();
    }
    int run = (t > 0) ? part[t - 1] : 0;
    #pragma unroll
    for (int i = 0; i < CH; i++) {
        int idx = base + i;
        if (idx < SCAN_GRID) { g_blkbase[idx] = run; run += g_blkcnt[idx]; }
    }
    if (t == 1023) g_cumRel[N_REL] = part[1023];
}

__global__ void scanSR_c_kernel() {
    int idx = blockIdx.x * SCAN_BLK + threadIdx.x;
    int lane = threadIdx.x & 31;
    int wid = threadIdx.x >> 5;
    int flag = (idx < NRN && g_cntSR[idx] > 0) ? 1 : 0;
    unsigned m = __ballot_sync(0xFFFFFFFFu, flag);
    int wpre = __popc(m & ((1u << lane) - 1));
    __shared__ int wsum[SCAN_BLK / 32];
    if (lane == 0) wsum[wid] = __popc(m);
    __syncthreads();
    int wbase = 0;
    #pragma unroll
    for (int w = 0; w < SCAN_BLK / 32; w++)
        if (w < wid) wbase += wsum[w];
    int rank = g_blkbase[blockIdx.x] + wbase + wpre;
    if (flag) g_jobrank[idx] = rank;
    if (idx < NRN && idx % N_NODES == 0) g_cumRel[idx / N_NODES] = rank;
}

__global__ void jb_kernel() {
    g_jb[0] = 0;
    int b = ROOTPAD;
    for (int r = 0; r < N_REL; r++) {
        g_jb[1 + r] = b;
        int c = g_cumRel[r + 1] - g_cumRel[r];
        b += (c + 127) & ~127;
    }
    g_jb[11] = b;
}

__global__ void jobinit_kernel() {
    int i = blockIdx.x * blockDim.x + threadIdx.x;
    if (i < NJMAX) g_joblist[i] = (i < N_NODES) ? i : 0;
}

__global__ void jobbuild_kernel() {
    int i = blockIdx.x * blockDim.x + threadIdx.x;
    if (i >= NRN) return;
    if (g_cntSR[i] > 0) {
        int r = i / N_NODES, src = i % N_NODES;
        int idx = g_jb[1 + r] + (g_jobrank[i] - g_cumRel[r]);
        g_joblist[idx] = src;
        g_jobidx[i] = idx * 64;        // u32 offset, premultiplied
    }
}

__global__ void fill_kernel(const int* __restrict__ ei, const int* __restrict__ et) {
    int e = blockIdx.x * blockDim.x + threadIdx.x;
    if (e >= N_EDGES) return;
    int src = ei[e];
    int dst = ei[N_EDGES + e];
    int r   = et[e];
    int pos = g_start[dst] + atomicAdd(&g_fill[dst], 1);
    float w = 1.0f / (float)g_cnt[dst * N_REL + r];
    g_epk[pos] = make_int2(g_jobidx[r * N_NODES + src], __float_as_int(w));
}

// pack weights TRANSPOSED as fp16: g_Bwh[l][rr][n][k] = W[k][n]
__global__ void bw_kernel(const float* __restrict__ rel_w, const float* __restrict__ root_w) {
    size_t idx = (size_t)blockIdx.x * blockDim.x + threadIdx.x;
    if (idx >= (size_t)N_LAYERS * 11 * 16384) return;
    int l = idx / (11 * 16384);
    int rem = idx % (11 * 16384);
    int rr = rem / 16384;
    int n = (rem % 16384) / 128, k = rem % 128;
    float v;
    if (rr == 0)
        v = root_w[(size_t)l * 16384 + k * 128 + n];
    else
        v = rel_w[(size_t)l * N_REL * 16384 + (size_t)(rr - 1) * 16384 + k * 128 + n];
    g_Bwh[idx] = __float2half_rn(v);
}

// ---------------- input projection (writes fp32 h and fp16 copy) ----------------
#define BM 64
#define BK 16
__global__ void proj_kernel(const float* __restrict__ x, const float* __restrict__ Wp,
                            const float* __restrict__ bp) {
    __shared__ float As[BK][BM + 4];
    __shared__ float Bs[BK][HIDDEN];
    int tid = threadIdx.x;
    int tm = tid >> 5, tn = tid & 31;
    int row0 = blockIdx.x * BM;
    float acc[8][4];
    #pragma unroll
    for (int i = 0; i < 8; i++)
        #pragma unroll
        for (int j = 0; j < 4; j++) acc[i][j] = 0.f;

    for (int k0 = 0; k0 < IN_DIM; k0 += BK) {
        {
            int r = tid >> 2, kc = (tid & 3) * 4, grow = row0 + r;
            float4 v = make_float4(0.f, 0.f, 0.f, 0.f);
            if (grow < N_NODES) v = *(const float4*)&x[(size_t)grow * IN_DIM + k0 + kc];
            As[kc + 0][r] = v.x; As[kc + 1][r] = v.y; As[kc + 2][r] = v.z; As[kc + 3][r] = v.w;
        }
        #pragma unroll
        for (int i = 0; i < 2; i++) {
            int f = tid + i * 256;
            int kk = f >> 5, c4 = (f & 31) * 4;
            *(float4*)&Bs[kk][c4] = *(const float4*)&Wp[(size_t)(k0 + kk) * HIDDEN + c4];
        }
        __syncthreads();
        #pragma unroll
        for (int kk = 0; kk < BK; kk++) {
            float a[8], b[4];
            *(float4*)&a[0] = *(const float4*)&As[kk][tm * 8];
            *(float4*)&a[4] = *(const float4*)&As[kk][tm * 8 + 4];
            *(float4*)&b[0] = *(const float4*)&Bs[kk][tn * 4];
            #pragma unroll
            for (int i = 0; i < 8; i++)
                #pragma unroll
                for (int j = 0; j < 4; j++) acc[i][j] = fmaf(a[i], b[j], acc[i][j]);
        }
        __syncthreads();
    }
    int n0 = tn * 4;
    float4 bb = *(const float4*)&bp[n0];
    #pragma unroll
    for (int i = 0; i < 8; i++) {
        int grow = row0 + tm * 8 + i;
        if (grow < N_NODES) {
            float4 o = make_float4(acc[i][0] + bb.x, acc[i][1] + bb.y,
                                   acc[i][2] + bb.z, acc[i][3] + bb.w);
            *(float4*)&g_h[0][(size_t)grow * HIDDEN + n0] = o;
            uint2 hv;
            hv.x = pack_h2(o.x, o.y);
            hv.y = pack_h2(o.z, o.w);
            *(uint2*)&g_hh[(size_t)grow * HIDDEN + n0] = hv;
        }
    }
}

// ---------------- compacted fp16 GEMM: g_Yc[job] = fp16(hh[joblist[job]] @ W[rel(job)]) ----------------
#define APH 72
#define BPH 72

__global__ void __launch_bounds__(256, 2)
gemmc_kernel(int l) {
    __shared__ __half As[128 * APH];     // [m][k-chunk]
    __shared__ __half Bs[128 * BPH];     // [n][k-chunk]
    __shared__ int rows[128];

    int jobs0 = blockIdx.x * 128;
    if (jobs0 >= g_jb[11]) return;
    int rr = 0;
    #pragma unroll
    for (int r = 1; r < 11; r++)
        if (jobs0 >= g_jb[r]) rr = r;

    int tid = threadIdx.x;
    int wid = tid >> 5;
    int lane = tid & 31;
    int gq = lane >> 2;
    int tq = lane & 3;
    int wm = (wid >> 1) * 32;
    int wn = (wid & 1) * 64;
    const __half* Bw = g_Bwh + ((size_t)l * 11 + rr) * 16384;

    if (tid < 128) rows[tid] = g_joblist[jobs0 + tid];
    __syncthreads();

    float c[2][8][4];
    #pragma unroll
    for (int mi = 0; mi < 2; mi++)
        #pragma unroll
        for (int nj = 0; nj < 8; nj++)
            #pragma unroll
            for (int q = 0; q < 4; q++) c[mi][nj][q] = 0.f;

    const uint32_t* AsU = (const uint32_t*)As;
    const uint32_t* BsU = (const uint32_t*)Bs;

    #pragma unroll
    for (int ch = 0; ch < 2; ch++) {
        int k0 = ch * 64;
        // A: 128 rows x 64 halves (fp16 direct). 1024 uint4 / 256 thr = 4 each.
        uint4 av[4];
        #pragma unroll
        for (int t = 0; t < 4; t++) {
            int idx = tid + t * 256;          // 0..1023
            int r = idx >> 3, u = idx & 7;
            av[t] = *(const uint4*)&g_hh[(size_t)rows[r] * HIDDEN + k0 + u * 8];
        }
        // B: 128 n-rows x 64 halves. 1024 uint4 / 256 thr = 4 each.
        uint4 bv[4];
        #pragma unroll
        for (int t = 0; t < 4; t++) {
            int idx = tid + t * 256;
            int n = idx >> 3, u = idx & 7;
            bv[t] = *(const uint4*)&Bw[(size_t)n * 128 + k0 + u * 8];
        }
        __syncthreads();    // previous chunk's mma done
        #pragma unroll
        for (int t = 0; t < 4; t++) {
            int idx = tid + t * 256;
            int r = idx >> 3, u = idx & 7;
            *(uint4*)&As[r * APH + u * 8] = av[t];
        }
        #pragma unroll
        for (int t = 0; t < 4; t++) {
            int idx = tid + t * 256;
            int n = idx >> 3, u = idx & 7;
            *(uint4*)&Bs[n * BPH + u * 8] = bv[t];
        }
        __syncthreads();

        // 4 k-steps of 16
        #pragma unroll
        for (int s = 0; s < 4; s++) {
            uint32_t a[2][4], b[8][2];
            #pragma unroll
            for (int mi = 0; mi < 2; mi++) {
                int r = wm + mi * 16 + gq;
                a[mi][0] = AsU[r * (APH / 2) + s * 8 + tq];
                a[mi][1] = AsU[(r + 8) * (APH / 2) + s * 8 + tq];
                a[mi][2] = AsU[r * (APH / 2) + s * 8 + tq + 4];
                a[mi][3] = AsU[(r + 8) * (APH / 2) + s * 8 + tq + 4];
            }
            #pragma unroll
            for (int nj = 0; nj < 8; nj++) {
                int n = wn + nj * 8 + gq;
                b[nj][0] = BsU[n * (BPH / 2) + s * 8 + tq];
                b[nj][1] = BsU[n * (BPH / 2) + s * 8 + tq + 4];
            }
            #pragma unroll
            for (int mi = 0; mi < 2; mi++)
                #pragma unroll
                for (int nj = 0; nj < 8; nj++)
                    mma_f16(c[mi][nj], a[mi], b[nj]);
        }
        __syncthreads();
    }

    // store to compact Y (fp16x2)
    #pragma unroll
    for (int mi = 0; mi < 2; mi++) {
        int j0 = jobs0 + wm + mi * 16 + gq;
        #pragma unroll
        for (int nj = 0; nj < 8; nj++) {
            int cb = wn + nj * 8 + 2 * tq;
            g_Yc[(size_t)j0 * 64 + (cb >> 1)]       = pack_h2(c[mi][nj][0], c[mi][nj][1]);
            g_Yc[(size_t)(j0 + 8) * 64 + (cb >> 1)] = pack_h2(c[mi][nj][2], c[mi][nj][3]);
        }
    }
}

// ---------------- fused CSR gather + bias + LN + ReLU + residual ----------------
__device__ __forceinline__ void fma_h2(float4& acc, uint2 v, float w) {
    float2 a = __half22float2(*(__half2*)&v.x);
    float2 b = __half22float2(*(__half2*)&v.y);
    acc.x = fmaf(a.x, w, acc.x);
    acc.y = fmaf(a.y, w, acc.y);
    acc.z = fmaf(b.x, w, acc.z);
    acc.w = fmaf(b.y, w, acc.w);
}

__global__ void gather_ln_kernel(const float* __restrict__ conv_b, const float* __restrict__ ln_g,
                                 const float* __restrict__ ln_b, int l, int cur) {
    int wid = threadIdx.x >> 5;
    int lane = threadIdx.x & 31;
    int row = blockIdx.x * 8 + wid;
    if (row >= N_NODES) return;
    int n0 = lane * 4;
    int lo2 = lane * 2;
    const float* hcur = g_h[cur];
    float* hnext = g_h[cur ^ 1];

    float4 acc;
    {
        uint2 rv = *(const uint2*)&g_Yc[(size_t)row * 64 + lo2];   // root job = identity
        float2 a = __half22float2(*(__half2*)&rv.x);
        float2 b = __half22float2(*(__half2*)&rv.y);
        float4 cb = *(const float4*)&conv_b[l * HIDDEN + n0];
        acc.x = a.x + cb.x; acc.y = a.y + cb.y; acc.z = b.x + cb.z; acc.w = b.y + cb.w;
    }

    int s = g_start[row];
    int e = s + g_cntd[row];
    int i = s;
    for (; i + 8 <= e; i += 8) {
        int2 p0 = g_epk[i],     p1 = g_epk[i + 1];
        int2 p2 = g_epk[i + 2], p3 = g_epk[i + 3];
        int2 p4 = g_epk[i + 4], p5 = g_epk[i + 5];
        int2 p6 = g_epk[i + 6], p7 = g_epk[i + 7];
        uint2 v0 = *(const uint2*)&g_Yc[(size_t)p0.x + lo2];
        uint2 v1 = *(const uint2*)&g_Yc[(size_t)p1.x + lo2];
        uint2 v2 = *(const uint2*)&g_Yc[(size_t)p2.x + lo2];
        uint2 v3 = *(const uint2*)&g_Yc[(size_t)p3.x + lo2];
        uint2 v4 = *(const uint2*)&g_Yc[(size_t)p4.x + lo2];
        uint2 v5 = *(const uint2*)&g_Yc[(size_t)p5.x + lo2];
        uint2 v6 = *(const uint2*)&g_Yc[(size_t)p6.x + lo2];
        uint2 v7 = *(const uint2*)&g_Yc[(size_t)p7.x + lo2];
        fma_h2(acc, v0, __int_as_float(p0.y));
        fma_h2(acc, v1, __int_as_float(p1.y));
        fma_h2(acc, v2, __int_as_float(p2.y));
        fma_h2(acc, v3, __int_as_float(p3.y));
        fma_h2(acc, v4, __int_as_float(p4.y));
        fma_h2(acc, v5, __int_as_float(p5.y));
        fma_h2(acc, v6, __int_as_float(p6.y));
        fma_h2(acc, v7, __int_as_float(p7.y));
    }
    for (; i < e; i++) {
        int2 p = g_epk[i];
        uint2 v = *(const uint2*)&g_Yc[(size_t)p.x + lo2];
        fma_h2(acc, v, __int_as_float(p.y));
    }

    float sm = acc.x + acc.y + acc.z + acc.w;
    float q = acc.x * acc.x + acc.y * acc.y + acc.z * acc.z + acc.w * acc.w;
    #pragma unroll
    for (int o = 16; o > 0; o >>= 1) {
        sm += __shfl_xor_sync(0xFFFFFFFFu, sm, o);
        q  += __shfl_xor_sync(0xFFFFFFFFu, q, o);
    }
    float mu = sm * (1.0f / HIDDEN);
    float var = q * (1.0f / HIDDEN) - mu * mu;
    float rs = rsqrtf(var + LN_EPS);
    float4 g4 = *(const float4*)&ln_g[l * HIDDEN + n0];
    float4 b4 = *(const float4*)&ln_b[l * HIDDEN + n0];
    float4 rv = *(const float4*)&hcur[(size_t)row * HIDDEN + n0];
    float4 o;
    o.x = fmaxf((acc.x - mu) * rs * g4.x + b4.x, 0.f) + rv.x;
    o.y = fmaxf((acc.y - mu) * rs * g4.y + b4.y, 0.f) + rv.y;
    o.z = fmaxf((acc.z - mu) * rs * g4.z + b4.z, 0.f) + rv.z;
    o.w = fmaxf((acc.w - mu) * rs * g4.w + b4.w, 0.f) + rv.w;
    *(float4*)&hnext[(size_t)row * HIDDEN + n0] = o;
    uint2 hv;
    hv.x = pack_h2(o.x, o.y);
    hv.y = pack_h2(o.z, o.w);
    *(uint2*)&g_hh[(size_t)row * HIDDEN + n0] = hv;
}

// ---------------- pooling ----------------
__device__ __forceinline__ int lower_bound_dev(const int* __restrict__ a, int n, int v) {
    int lo = 0, hi = n;
    while (lo < hi) { int mid = (lo + hi) >> 1; if (a[mid] < v) lo = mid + 1; else hi = mid; }
    return lo;
}

__global__ void pool_kernel(const int* __restrict__ batch, float* __restrict__ out, int finalbuf) {
    int g = blockIdx.x;
    int tid = threadIdx.x;
    int start = lower_bound_dev(batch, N_NODES, g);
    int end   = lower_bound_dev(batch, N_NODES, g + 1);
    const float* h = g_h[finalbuf];
    float acc = 0.f;
    for (int i = start; i < end; i++)
        acc += h[(size_t)i * HIDDEN + tid];
    out[g * HIDDEN + tid] = acc;
}

// ---------------- launch ----------------
extern "C" void kernel_launch(void* const* d_in, const int* in_sizes, int n_in,
                              void* d_out, int out_size) {
    const float* x      = (const float*)d_in[0];
    const int* ei       = (const int*)d_in[1];
    const int* et       = (const int*)d_in[2];
    const int* batch    = (const int*)d_in[3];
    const float* Wp     = (const float*)d_in[4];
    const float* bp     = (const float*)d_in[5];
    const float* rel_w  = (const float*)d_in[6];
    const float* root_w = (const float*)d_in[7];
    const float* conv_b = (const float*)d_in[8];
    const float* ln_g   = (const float*)d_in[9];
    const float* ln_b   = (const float*)d_in[10];
    float* out = (float*)d_out;

    // structure setup
    init_kernel<<<(NRN + 255) / 256, 256>>>();
    count_kernel<<<(N_EDGES + 255) / 256, 256>>>(ei, et);
    scan_dst_kernel<<<1, 1024>>>();
    scanSR_a_kernel<<<SCAN_GRID, SCAN_BLK>>>();
    scanSR_b_kernel<<<1, 1024>>>();
    scanSR_c_kernel<<<SCAN_GRID, SCAN_BLK>>>();
    jb_kernel<<<1, 1>>>();
    jobinit_kernel<<<(NJMAX + 255) / 256, 256>>>();
    jobbuild_kernel<<<(NRN + 255) / 256, 256>>>();
    fill_kernel<<<(N_EDGES + 255) / 256, 256>>>(ei, et);

    // weights packed once for all layers (fp16, transposed)
    bw_kernel<<<(int)(((size_t)N_LAYERS * 11 * 16384 + 255) / 256), 256>>>(rel_w, root_w);

    proj_kernel<<<(N_NODES + BM - 1) / BM, 256>>>(x, Wp, bp);

    for (int l = 0; l < N_LAYERS; l++) {
        int cur = l & 1;
        gemmc_kernel<<<MAXTILES, 256>>>(l);
        gather_ln_kernel<<<(N_NODES + 7) / 8, 256>>>(conv_b, ln_g, ln_b, l, cur);
    }

    pool_kernel<<<N_GRAPHS, HIDDEN>>>(batch, out, 0);
}

// round 16
// speedup vs baseline: 2.1273x; 1.0081x over previous
#include <cuda_runtime.h>
#include <cuda_fp16.h>
#include <cstdint>

#define N_NODES 50000
#define N_EDGES 600000
#define IN_DIM  64
#define HIDDEN  128
#define N_REL   10
#define N_LAYERS 6
#define N_GRAPHS 64
#define LN_EPS  1e-5f

#define NRN     (N_REL * N_NODES)          // 500000 (rel,src) slots
#define ROOTPAD 50048                      // pad128(50000)
#define NJMAX   (ROOTPAD * 11)             // worst-case padded job rows = 550528
#define MAXTILES (NJMAX / 128)             // 4301

#define SCAN_BLK  256
#define SCAN_GRID ((NRN + SCAN_BLK - 1) / SCAN_BLK)   // 1954

// ---------------- device scratch ----------------
__device__ uint32_t g_Yc[(size_t)NJMAX * 64];      // compact Y, fp16x2 per u32 (<=141MB)
__device__ float g_h[2][(size_t)N_NODES * HIDDEN]; // ping-pong features (fp32)
__device__ __half g_hh[(size_t)N_NODES * HIDDEN];  // fp16 copy of current h (GEMM A side)
__device__ __half g_Bwh[(size_t)N_LAYERS * 11 * 128 * 128]; // fp16 weights [l][rr][n][k] (transposed)
__device__ int   g_cnt[N_NODES * N_REL];           // in-degree per (dst,rel)
__device__ int   g_cntSR[NRN];                     // out-degree per (rel,src)
__device__ int   g_cntd[N_NODES];                  // per-dst in-degree
__device__ int   g_start[N_NODES];                 // CSR offsets (by dst)
__device__ int   g_fill[N_NODES];                  // CSR fill cursors
__device__ int   g_jobrank[NRN];
__device__ int   g_cumRel[N_REL + 1];
__device__ int   g_jb[12];
__device__ int   g_joblist[NJMAX];
__device__ int   g_jobidx[NRN];
__device__ int2  g_epk[N_EDGES];                   // per-edge packed {coff, cw bits}
__device__ int   g_blkcnt[SCAN_GRID];
__device__ int   g_blkbase[SCAN_GRID];

__device__ __forceinline__ uint32_t pack_h2(float lo, float hi) {
    __half2 h = __floats2half2_rn(lo, hi);
    return *(uint32_t*)&h;
}

__device__ __forceinline__ uint32_t smem_u32(const void* p) {
    uint32_t a;
    asm("{ .reg .u64 t; cvta.to.shared.u64 t, %1; cvt.u32.u64 %0, t; }" : "=r"(a) : "l"(p));
    return a;
}

__device__ __forceinline__ void mma_f16(float* c, const uint32_t* a, const uint32_t* b) {
    asm volatile(
        "mma.sync.aligned.m16n8k16.row.col.f32.f16.f16.f32 "
        "{%0,%1,%2,%3}, {%4,%5,%6,%7}, {%8,%9}, {%0,%1,%2,%3};"
        : "+f"(c[0]), "+f"(c[1]), "+f"(c[2]), "+f"(c[3])
        : "r"(a[0]), "r"(a[1]), "r"(a[2]), "r"(a[3]), "r"(b[0]), "r"(b[1]));
}

#define LDM_X4(r0, r1, r2, r3, addr) \
    asm volatile("ldmatrix.sync.aligned.m8n8.x4.shared.b16 {%0,%1,%2,%3}, [%4];" \
                 : "=r"(r0), "=r"(r1), "=r"(r2), "=r"(r3) : "r"(addr))

// ---------------- setup kernels (once per call) ----------------
__global__ void init_kernel() {
    int i = blockIdx.x * blockDim.x + threadIdx.x;
    if (i < NRN) { g_cntSR[i] = 0; }
    if (i < N_NODES * N_REL) g_cnt[i] = 0;
    if (i < N_NODES) { g_cntd[i] = 0; g_fill[i] = 0; }
}

__global__ void count_kernel(const int* __restrict__ ei, const int* __restrict__ et) {
    int e = blockIdx.x * blockDim.x + threadIdx.x;
    if (e >= N_EDGES) return;
    int src = ei[e];
    int dst = ei[N_EDGES + e];
    int r = et[e];
    atomicAdd(&g_cnt[dst * N_REL + r], 1);
    atomicAdd(&g_cntSR[r * N_NODES + src], 1);
    atomicAdd(&g_cntd[dst], 1);
}

__global__ void scan_dst_kernel() {
    __shared__ int part[1024];
    int t = threadIdx.x;
    const int CH = (N_NODES + 1023) / 1024;
    int base = t * CH;
    int s = 0;
    for (int i = 0; i < CH; i++) {
        int idx = base + i;
        if (idx < N_NODES) s += g_cntd[idx];
    }
    part[t] = s;
    __syncthreads();
    for (int off = 1; off < 1024; off <<= 1) {
        int v = (t >= off) ? part[t - off] : 0;
        __syncthreads();
        part[t] += v;
        __syncthreads();
    }
    int run = (t > 0) ? part[t - 1] : 0;
    for (int i = 0; i < CH; i++) {
        int idx = base + i;
        if (idx < N_NODES) { g_start[idx] = run; run += g_cntd[idx]; }
    }
}

__global__ void scanSR_a_kernel() {
    int idx = blockIdx.x * SCAN_BLK + threadIdx.x;
    int lane = threadIdx.x & 31;
    int wid = threadIdx.x >> 5;
    int flag = (idx < NRN && g_cntSR[idx] > 0) ? 1 : 0;
    unsigned m = __ballot_sync(0xFFFFFFFFu, flag);
    __shared__ int wsum[SCAN_BLK / 32];
    if (lane == 0) wsum[wid] = __popc(m);
    __syncthreads();
    if (threadIdx.x == 0) {
        int s = 0;
        #pragma unroll
        for (int w = 0; w < SCAN_BLK / 32; w++) s += wsum[w];
        g_blkcnt[blockIdx.x] = s;
    }
}

__global__ void scanSR_b_kernel() {
    __shared__ int part[1024];
    int t = threadIdx.x;
    const int CH = (SCAN_GRID + 1023) / 1024;   // 2
    int base = t * CH;
    int s = 0;
    #pragma unroll
    for (int i = 0; i < CH; i++) {
        int idx = base + i;
        if (idx < SCAN_GRID) s += g_blkcnt[idx];
    }
    part[t] = s;
    __syncthreads();
    for (int off = 1; off < 1024; off <<= 1) {
        int v = (t >= off) ? part[t - off] : 0;
        __syncthreads();
        part[t] += v;
        __syncthreads();
    }
    int run = (t > 0) ? part[t - 1] : 0;
    #pragma unroll
    for (int i = 0; i < CH; i++) {
        int idx = base + i;
        if (idx < SCAN_GRID) { g_blkbase[idx] = run; run += g_blkcnt[idx]; }
    }
    if (t == 1023) g_cumRel[N_REL] = part[1023];
}

__global__ void scanSR_c_kernel() {
    int idx = blockIdx.x * SCAN_BLK + threadIdx.x;
    int lane = threadIdx.x & 31;
    int wid = threadIdx.x >> 5;
    int flag = (idx < NRN && g_cntSR[idx] > 0) ? 1 : 0;
    unsigned m = __ballot_sync(0xFFFFFFFFu, flag);
    int wpre = __popc(m & ((1u << lane) - 1));
    __shared__ int wsum[SCAN_BLK / 32];
    if (lane == 0) wsum[wid] = __popc(m);
    __syncthreads();
    int wbase = 0;
    #pragma unroll
    for (int w = 0; w < SCAN_BLK / 32; w++)
        if (w < wid) wbase += wsum[w];
    int rank = g_blkbase[blockIdx.x] + wbase + wpre;
    if (flag) g_jobrank[idx] = rank;
    if (idx < NRN && idx % N_NODES == 0) g_cumRel[idx / N_NODES] = rank;
}

__global__ void jb_kernel() {
    g_jb[0] = 0;
    int b = ROOTPAD;
    for (int r = 0; r < N_REL; r++) {
        g_jb[1 + r] = b;
        int c = g_cumRel[r + 1] - g_cumRel[r];
        b += (c + 127) & ~127;
    }
    g_jb[11] = b;
}

__global__ void jobinit_kernel() {
    int i = blockIdx.x * blockDim.x + threadIdx.x;
    if (i < NJMAX) g_joblist[i] = (i < N_NODES) ? i : 0;
}

__global__ void jobbuild_kernel() {
    int i = blockIdx.x * blockDim.x + threadIdx.x;
    if (i >= NRN) return;
    if (g_cntSR[i] > 0) {
        int r = i / N_NODES, src = i % N_NODES;
        int idx = g_jb[1 + r] + (g_jobrank[i] - g_cumRel[r]);
        g_joblist[idx] = src;
        g_jobidx[i] = idx * 64;        // u32 offset, premultiplied
    }
}

__global__ void fill_kernel(const int* __restrict__ ei, const int* __restrict__ et) {
    int e = blockIdx.x * blockDim.x + threadIdx.x;
    if (e >= N_EDGES) return;
    int src = ei[e];
    int dst = ei[N_EDGES + e];
    int r   = et[e];
    int pos = g_start[dst] + atomicAdd(&g_fill[dst], 1);
    float w = 1.0f / (float)g_cnt[dst * N_REL + r];
    g_epk[pos] = make_int2(g_jobidx[r * N_NODES + src], __float_as_int(w));
}

// pack weights TRANSPOSED as fp16: g_Bwh[l][rr][n][k] = W[k][n]
__global__ void bw_kernel(const float* __restrict__ rel_w, const float* __restrict__ root_w) {
    size_t idx = (size_t)blockIdx.x * blockDim.x + threadIdx.x;
    if (idx >= (size_t)N_LAYERS * 11 * 16384) return;
    int l = idx / (11 * 16384);
    int rem = idx % (11 * 16384);
    int rr = rem / 16384;
    int n = (rem % 16384) / 128, k = rem % 128;
    float v;
    if (rr == 0)
        v = root_w[(size_t)l * 16384 + k * 128 + n];
    else
        v = rel_w[(size_t)l * N_REL * 16384 + (size_t)(rr - 1) * 16384 + k * 128 + n];
    g_Bwh[idx] = __float2half_rn(v);
}

// ---------------- input projection (writes fp32 h and fp16 copy) ----------------
#define BM 64
#define BK 16
__global__ void proj_kernel(const float* __restrict__ x, const float* __restrict__ Wp,
                            const float* __restrict__ bp) {
    __shared__ float As[BK][BM + 4];
    __shared__ float Bs[BK][HIDDEN];
    int tid = threadIdx.x;
    int tm = tid >> 5, tn = tid & 31;
    int row0 = blockIdx.x * BM;
    float acc[8][4];
    #pragma unroll
    for (int i = 0; i < 8; i++)
        #pragma unroll
        for (int j = 0; j < 4; j++) acc[i][j] = 0.f;

    for (int k0 = 0; k0 < IN_DIM; k0 += BK) {
        {
            int r = tid >> 2, kc = (tid & 3) * 4, grow = row0 + r;
            float4 v = make_float4(0.f, 0.f, 0.f, 0.f);
            if (grow < N_NODES) v = *(const float4*)&x[(size_t)grow * IN_DIM + k0 + kc];
            As[kc + 0][r] = v.x; As[kc + 1][r] = v.y; As[kc + 2][r] = v.z; As[kc + 3][r] = v.w;
        }
        #pragma unroll
        for (int i = 0; i < 2; i++) {
            int f = tid + i * 256;
            int kk = f >> 5, c4 = (f & 31) * 4;
            *(float4*)&Bs[kk][c4] = *(const float4*)&Wp[(size_t)(k0 + kk) * HIDDEN + c4];
        }
        __syncthreads();
        #pragma unroll
        for (int kk = 0; kk < BK; kk++) {
            float a[8], b[4];
            *(float4*)&a[0] = *(const float4*)&As[kk][tm * 8];
            *(float4*)&a[4] = *(const float4*)&As[kk][tm * 8 + 4];
            *(float4*)&b[0] = *(const float4*)&Bs[kk][tn * 4];
            #pragma unroll
            for (int i = 0; i < 8; i++)
                #pragma unroll
                for (int j = 0; j < 4; j++) acc[i][j] = fmaf(a[i], b[j], acc[i][j]);
        }
        __syncthreads();
    }
    int n0 = tn * 4;
    float4 bb = *(const float4*)&bp[n0];
    #pragma unroll
    for (int i = 0; i < 8; i++) {
        int grow = row0 + tm * 8 + i;
        if (grow < N_NODES) {
            float4 o = make_float4(acc[i][0] + bb.x, acc[i][1] + bb.y,
                                   acc[i][2] + bb.z, acc[i][3] + bb.w);
            *(float4*)&g_h[0][(size_t)grow * HIDDEN + n0] = o;
            uint2 hv;
            hv.x = pack_h2(o.x, o.y);
            hv.y = pack_h2(o.z, o.w);
            *(uint2*)&g_hh[(size_t)grow * HIDDEN + n0] = hv;
        }
    }
}

// ---------------- compacted fp16 GEMM with ldmatrix fragment loads ----------------
#define APH 72
#define BPH 72

__global__ void __launch_bounds__(256, 2)
gemmc_kernel(int l) {
    __shared__ __half As[128 * APH];     // [m][k-chunk]
    __shared__ __half Bs[128 * BPH];     // [n][k-chunk]
    __shared__ int rows[128];

    int jobs0 = blockIdx.x * 128;
    if (jobs0 >= g_jb[11]) return;
    int rr = 0;
    #pragma unroll
    for (int r = 1; r < 11; r++)
        if (jobs0 >= g_jb[r]) rr = r;

    int tid = threadIdx.x;
    int wid = tid >> 5;
    int lane = tid & 31;
    int gq = lane >> 2;
    int tq = lane & 3;
    int wm = (wid >> 1) * 32;
    int wn = (wid & 1) * 64;
    const __half* Bw = g_Bwh + ((size_t)l * 11 + rr) * 16384;

    if (tid < 128) rows[tid] = g_joblist[jobs0 + tid];
    __syncthreads();

    float c[2][8][4];
    #pragma unroll
    for (int mi = 0; mi < 2; mi++)
        #pragma unroll
        for (int nj = 0; nj < 8; nj++)
            #pragma unroll
            for (int q = 0; q < 4; q++) c[mi][nj][q] = 0.f;

    // ldmatrix base addresses (bytes); step +32B per k16-step
    uint32_t aAddr[2], bAddr[4];
    {
        uint32_t asBase = smem_u32(As);
        uint32_t bsBase = smem_u32(Bs);
        int arow = wm + (lane & 15);
        int akof = (lane >> 4) * 8;
        #pragma unroll
        for (int mi = 0; mi < 2; mi++)
            aAddr[mi] = asBase + (uint32_t)(((arow + mi * 16) * APH + akof) * 2);
        int bn = ((lane >> 4) << 3) + (lane & 7);
        int bkof = ((lane >> 3) & 1) * 8;
        #pragma unroll
        for (int j = 0; j < 4; j++)
            bAddr[j] = bsBase + (uint32_t)(((wn + 16 * j + bn) * BPH + bkof) * 2);
    }

    #pragma unroll
    for (int ch = 0; ch < 2; ch++) {
        int k0 = ch * 64;
        uint4 av[4];
        #pragma unroll
        for (int t = 0; t < 4; t++) {
            int idx = tid + t * 256;          // 0..1023
            int r = idx >> 3, u = idx & 7;
            av[t] = *(const uint4*)&g_hh[(size_t)rows[r] * HIDDEN + k0 + u * 8];
        }
        uint4 bv[4];
        #pragma unroll
        for (int t = 0; t < 4; t++) {
            int idx = tid + t * 256;
            int n = idx >> 3, u = idx & 7;
            bv[t] = *(const uint4*)&Bw[(size_t)n * 128 + k0 + u * 8];
        }
        __syncthreads();    // previous chunk's mma done
        #pragma unroll
        for (int t = 0; t < 4; t++) {
            int idx = tid + t * 256;
            int r = idx >> 3, u = idx & 7;
            *(uint4*)&As[r * APH + u * 8] = av[t];
        }
        #pragma unroll
        for (int t = 0; t < 4; t++) {
            int idx = tid + t * 256;
            int n = idx >> 3, u = idx & 7;
            *(uint4*)&Bs[n * BPH + u * 8] = bv[t];
        }
        __syncthreads();

        // 4 k-steps of 16 via ldmatrix.x4
        #pragma unroll
        for (int s = 0; s < 4; s++) {
            uint32_t koff = (uint32_t)(s * 32);   // 16 halves = 32 bytes
            uint32_t a[2][4], b[8][2];
            #pragma unroll
            for (int mi = 0; mi < 2; mi++)
                LDM_X4(a[mi][0], a[mi][1], a[mi][2], a[mi][3], aAddr[mi] + koff);
            #pragma unroll
            for (int j = 0; j < 4; j++)
                LDM_X4(b[2 * j][0], b[2 * j][1], b[2 * j + 1][0], b[2 * j + 1][1],
                       bAddr[j] + koff);
            #pragma unroll
            for (int mi = 0; mi < 2; mi++)
                #pragma unroll
                for (int nj = 0; nj < 8; nj++)
                    mma_f16(c[mi][nj], a[mi], b[nj]);
        }
        __syncthreads();
    }

    // store to compact Y (fp16x2)
    #pragma unroll
    for (int mi = 0; mi < 2; mi++) {
        int j0 = jobs0 + wm + mi * 16 + gq;
        #pragma unroll
        for (int nj = 0; nj < 8; nj++) {
            int cb = wn + nj * 8 + 2 * tq;
            g_Yc[(size_t)j0 * 64 + (cb >> 1)]       = pack_h2(c[mi][nj][0], c[mi][nj][1]);
            g_Yc[(size_t)(j0 + 8) * 64 + (cb >> 1)] = pack_h2(c[mi][nj][2], c[mi][nj][3]);
        }
    }
}

// ---------------- fused CSR gather + bias + LN + ReLU + residual ----------------
__device__ __forceinline__ void fma_h2(float4& acc, uint2 v, float w) {
    float2 a = __half22float2(*(__half2*)&v.x);
    float2 b = __half22float2(*(__half2*)&v.y);
    acc.x = fmaf(a.x, w, acc.x);
    acc.y = fmaf(a.y, w, acc.y);
    acc.z = fmaf(b.x, w, acc.z);
    acc.w = fmaf(b.y, w, acc.w);
}

__global__ void gather_ln_kernel(const float* __restrict__ conv_b, const float* __restrict__ ln_g,
                                 const float* __restrict__ ln_b, int l, int cur) {
    int wid = threadIdx.x >> 5;
    int lane = threadIdx.x & 31;
    int row = blockIdx.x * 8 + wid;
    if (row >= N_NODES) return;
    int n0 = lane * 4;
    int lo2 = lane * 2;
    const float* hcur = g_h[cur];
    float* hnext = g_h[cur ^ 1];

    float4 acc;
    {
        uint2 rv = *(const uint2*)&g_Yc[(size_t)row * 64 + lo2];   // root job = identity
        float2 a = __half22float2(*(__half2*)&rv.x);
        float2 b = __half22float2(*(__half2*)&rv.y);
        float4 cb = *(const float4*)&conv_b[l * HIDDEN + n0];
        acc.x = a.x + cb.x; acc.y = a.y + cb.y; acc.z = b.x + cb.z; acc.w = b.y + cb.w;
    }

    int s = g_start[row];
    int e = s + g_cntd[row];
    int i = s;
    for (; i + 8 <= e; i += 8) {
        int2 p0 = g_epk[i],     p1 = g_epk[i + 1];
        int2 p2 = g_epk[i + 2], p3 = g_epk[i + 3];
        int2 p4 = g_epk[i + 4], p5 = g_epk[i + 5];
        int2 p6 = g_epk[i + 6], p7 = g_epk[i + 7];
        uint2 v0 = *(const uint2*)&g_Yc[(size_t)p0.x + lo2];
        uint2 v1 = *(const uint2*)&g_Yc[(size_t)p1.x + lo2];
        uint2 v2 = *(const uint2*)&g_Yc[(size_t)p2.x + lo2];
        uint2 v3 = *(const uint2*)&g_Yc[(size_t)p3.x + lo2];
        uint2 v4 = *(const uint2*)&g_Yc[(size_t)p4.x + lo2];
        uint2 v5 = *(const uint2*)&g_Yc[(size_t)p5.x + lo2];
        uint2 v6 = *(const uint2*)&g_Yc[(size_t)p6.x + lo2];
        uint2 v7 = *(const uint2*)&g_Yc[(size_t)p7.x + lo2];
        fma_h2(acc, v0, __int_as_float(p0.y));
        fma_h2(acc, v1, __int_as_float(p1.y));
        fma_h2(acc, v2, __int_as_float(p2.y));
        fma_h2(acc, v3, __int_as_float(p3.y));
        fma_h2(acc, v4, __int_as_float(p4.y));
        fma_h2(acc, v5, __int_as_float(p5.y));
        fma_h2(acc, v6, __int_as_float(p6.y));
        fma_h2(acc, v7, __int_as_float(p7.y));
    }
    for (; i < e; i++) {
        int2 p = g_epk[i];
        uint2 v = *(const uint2*)&g_Yc[(size_t)p.x + lo2];
        fma_h2(acc, v, __int_as_float(p.y));
    }

    float sm = acc.x + acc.y + acc.z + acc.w;
    float q = acc.x * acc.x + acc.y * acc.y + acc.z * acc.z + acc.w * acc.w;
    #pragma unroll
    for (int o = 16; o > 0; o >>= 1) {
        sm += __shfl_xor_sync(0xFFFFFFFFu, sm, o);
        q  += __shfl_xor_sync(0xFFFFFFFFu, q, o);
    }
    float mu = sm * (1.0f / HIDDEN);
    float var = q * (1.0f / HIDDEN) - mu * mu;
    float rs = rsqrtf(var + LN_EPS);
    float4 g4 = *(const float4*)&ln_g[l * HIDDEN + n0];
    float4 b4 = *(const float4*)&ln_b[l * HIDDEN + n0];
    float4 rv = *(const float4*)&hcur[(size_t)row * HIDDEN + n0];
    float4 o;
    o.x = fmaxf((acc.x - mu) * rs * g4.x + b4.x, 0.f) + rv.x;
    o.y = fmaxf((acc.y - mu) * rs * g4.y + b4.y, 0.f) + rv.y;
    o.z = fmaxf((acc.z - mu) * rs * g4.z + b4.z, 0.f) + rv.z;
    o.w = fmaxf((acc.w - mu) * rs * g4.w + b4.w, 0.f) + rv.w;
    *(float4*)&hnext[(size_t)row * HIDDEN + n0] = o;
    uint2 hv;
    hv.x = pack_h2(o.x, o.y);
    hv.y = pack_h2(o.z, o.w);
    *(uint2*)&g_hh[(size_t)row * HIDDEN + n0] = hv;
}

// ---------------- pooling ----------------
__device__ __forceinline__ int lower_bound_dev(const int* __restrict__ a, int n, int v) {
    int lo = 0, hi = n;
    while (lo < hi) { int mid = (lo + hi) >> 1; if (a[mid] < v) lo = mid + 1; else hi = mid; }
    return lo;
}

__global__ void pool_kernel(const int* __restrict__ batch, float* __restrict__ out, int finalbuf) {
    int g = blockIdx.x;
    int tid = threadIdx.x;
    int start = lower_bound_dev(batch, N_NODES, g);
    int end   = lower_bound_dev(batch, N_NODES, g + 1);
    const float* h = g_h[finalbuf];
    float acc = 0.f;
    for (int i = start; i < end; i++)
        acc += h[(size_t)i * HIDDEN + tid];
    out[g * HIDDEN + tid] = acc;
}

// ---------------- launch ----------------
extern "C" void kernel_launch(void* const* d_in, const int* in_sizes, int n_in,
                              void* d_out, int out_size) {
    const float* x      = (const float*)d_in[0];
    const int* ei       = (const int*)d_in[1];
    const int* et       = (const int*)d_in[2];
    const int* batch    = (const int*)d_in[3];
    const float* Wp     = (const float*)d_in[4];
    const float* bp     = (const float*)d_in[5];
    const float* rel_w  = (const float*)d_in[6];
    const float* root_w = (const float*)d_in[7];
    const float* conv_b = (const float*)d_in[8];
    const float* ln_g   = (const float*)d_in[9];
    const float* ln_b   = (const float*)d_in[10];
    float* out = (float*)d_out;

    // structure setup
    init_kernel<<<(NRN + 255) / 256, 256>>>();
    count_kernel<<<(N_EDGES + 255) / 256, 256>>>(ei, et);
    scan_dst_kernel<<<1, 1024>>>();
    scanSR_a_kernel<<<SCAN_GRID, SCAN_BLK>>>();
    scanSR_b_kernel<<<1, 1024>>>();
    scanSR_c_kernel<<<SCAN_GRID, SCAN_BLK>>>();
    jb_kernel<<<1, 1>>>();
    jobinit_kernel<<<(NJMAX + 255) / 256, 256>>>();
    jobbuild_kernel<<<(NRN + 255) / 256, 256>>>();
    fill_kernel<<<(N_EDGES + 255) / 256, 256>>>(ei, et);

    // weights packed once for all layers (fp16, transposed)
    bw_kernel<<<(int)(((size_t)N_LAYERS * 11 * 16384 + 255) / 256), 256>>>(rel_w, root_w);

    proj_kernel<<<(N_NODES + BM - 1) / BM, 256>>>(x, Wp, bp);

    for (int l = 0; l < N_LAYERS; l++) {
        int cur = l & 1;
        gemmc_kernel<<<MAXTILES, 256>>>(l);
        gather_ln_kernel<<<(N_NODES + 7) / 8, 256>>>(conv_b, ln_g, ln_b, l, cur);
    }

    pool_kernel<<<N_GRAPHS, HIDDEN>>>(batch, out, 0);
}